// round 9
// baseline (speedup 1.0000x reference)
#include <cuda_runtime.h>
#include <cuda_fp16.h>
#include <math.h>
#include <stdint.h>

#define N_BATCH 4
#define CIN     512
#define HWPIX   4096
#define NA      36864
#define NPRE    6000
#define NPOST   300
#define NCHUNK  94
#define NPAD    6016
#define SORTN   8192
#define PADPX   4356      // 66*66

#define LOCS_OFF   0
#define SCORES_OFF 589824
#define ROIS_OFF   884736
#define RIND_OFF   889536
#define ANCH_OFF   890736

// conv smem: A tile 128x144B + B tile 64x144B per stage, 2 stages; master 32x256 floats.
// Padded total to force 1 CTA/SM (wave balance: 1024 CTAs / 148 SMs = 6.92 -> 7 waves, 98.9%).
#define STAGE_BYTES  27648
#define MASTER_OFF_F (128 + 2 * STAGE_BYTES / 4)     // float index: 128 + 13824
#define CONV_SMEM    122880

// ---------------- scratch ----------------
__device__ float               g_h[N_BATCH * CIN * HWPIX];
__device__ __half              g_xs[(size_t)N_BATCH * 2 * PADPX * CIN];   // fp16 hi / lo*4096
__device__ __half              g_wsf[(size_t)2 * 9 * CIN * CIN];
__device__ float               g_fg[N_BATCH * NA];
__device__ float4              g_boxes[N_BATCH * NA];
__device__ unsigned            g_keys[N_BATCH * NA];
__device__ unsigned            g_cut[N_BATCH];
__device__ int                 g_cnt[N_BATCH];
__device__ unsigned long long  g_sel[N_BATCH][SORTN];
__device__ float4              g_bsort[N_BATCH][NPAD];
__device__ unsigned long long  g_masks[N_BATCH][NPAD][NCHUNK];

// ---------------- helpers ----------------
__device__ __forceinline__ uint32_t smem_u32(const void* p) {
    uint32_t a;
    asm("{ .reg .u64 t; cvta.to.shared.u64 t, %1; cvt.u32.u64 %0, t; }" : "=r"(a) : "l"(p));
    return a;
}
__device__ __forceinline__ unsigned f2key(float f) {
    unsigned u = __float_as_uint(f);
    return (u & 0x80000000u) ? ~u : (u | 0x80000000u);
}
__device__ __forceinline__ void anchor_base(int a, float* out) {
    const double ratios[3] = {0.5, 1.0, 2.0};
    const double scales[3] = {8.0, 16.0, 32.0};
    int ri = a / 3, si = a % 3;
    double h = 16.0 * scales[si] * sqrt(ratios[ri]);
    double w = 16.0 * scales[si] * sqrt(1.0 / ratios[ri]);
    out[0] = (float)(8.0 - h * 0.5);
    out[1] = (float)(8.0 - w * 0.5);
    out[2] = (float)(8.0 + h * 0.5);
    out[3] = (float)(8.0 + w * 0.5);
}

// ---------------- init ----------------
__global__ void init_k() {
    int idx = blockIdx.x * 256 + threadIdx.x;
    if (idx < N_BATCH) g_cnt[idx] = 0;
    if (idx < N_BATCH * SORTN) (&g_sel[0][0])[idx] = 0ull;
}

__global__ void xzero_k() {
    size_t idx = (size_t)blockIdx.x * 256 + threadIdx.x;
    size_t total = (size_t)N_BATCH * 2 * PADPX * CIN / 4;  // u64 chunks of halves
    if (idx < total) ((unsigned long long*)g_xs)[idx] = 0ull;
}

// split W1 -> g_wsf[s][tap][oc][ic]  (fp16 hi, lo*4096)
__global__ void wsplit_k(const float* __restrict__ W1) {
    int e = blockIdx.x * 256 + threadIdx.x;
    if (e >= 9 * CIN * CIN) return;
    int t = e / (CIN * CIN);
    int oi = e - t * (CIN * CIN);
    int oc = oi >> 9, ic = oi & 511;
    float w = W1[((size_t)oc * CIN + ic) * 9 + t];
    __half hi = __float2half(w);
    float lo = (w - __half2float(hi)) * 4096.f;
    size_t o = ((size_t)t * CIN + oc) * CIN + ic;
    g_wsf[o] = hi;
    g_wsf[o + (size_t)9 * CIN * CIN] = __float2half(lo);
}

// transpose + split x -> g_xs[n][s][prow*66+pcol][ic], interior at +1 offset
__global__ __launch_bounds__(256) void xsplit_k(const float* __restrict__ x) {
    __shared__ float s[64][65];
    int row = blockIdx.x, ic0 = blockIdx.y * 64, n = blockIdx.z;
    int tid = threadIdx.x;
    #pragma unroll
    for (int k = 0; k < 16; k++) {
        int idx = tid + k * 256;
        int ic_l = idx >> 6, p = idx & 63;
        s[ic_l][p] = x[((size_t)(n * CIN + ic0 + ic_l) << 12) + row * 64 + p];
    }
    __syncthreads();
    #pragma unroll
    for (int k = 0; k < 16; k++) {
        int idx = tid + k * 256;
        int p = idx >> 6, ic_l = idx & 63;
        float v = s[ic_l][p];
        __half hi = __float2half(v);
        float lo = (v - __half2float(hi)) * 4096.f;
        int prow = (row + 1) * 66 + (p + 1);
        size_t b = ((size_t)(n * 2) * PADPX + prow) * CIN + ic0 + ic_l;
        g_xs[b] = hi;
        g_xs[b + (size_t)PADPX * CIN] = __float2half(lo);
    }
}

// ---------------- conv3x3 via mma.sync fp16 3-term (scaled limbs), chunked accumulation ----------------
// grid (32 px-tiles, 8 oc-blocks, 4 n) = 1024 CTAs, 256 threads (8 warps: 4m x 2n).
// Block tile 128px x 64oc; warp tile 32px x 32oc. 216 iters (72 hh + 144 corr), K=64 ic each.
__device__ __forceinline__ void conv_issue(int iter, uint32_t dstbase,
                                           int tid, int blkpx, int blkoc, int n) {
    int ph = iter / 72;
    int rem = iter - ph * 72;
    int tap = rem >> 3;
    int icc = (rem & 7) * 64;
    int ky = tap / 3, kx = tap - ky * 3;
    int sAs = (ph == 2) ? 1 : 0;
    int sWs = (ph == 1) ? 1 : 0;
    const __half* xbase = g_xs + (((size_t)(n * 2 + sAs)) * PADPX << 9) + icc;
    #pragma unroll
    for (int r = 0; r < 4; r++) {
        int idx = tid + r * 256;
        int arow = idx >> 3, q = idx & 7;
        int p = blkpx * 128 + arow;
        int ppix = ((p >> 6) + ky) * 66 + (p & 63) + kx;
        const __half* src = xbase + ((size_t)ppix << 9) + q * 8;
        uint32_t dst = dstbase + (uint32_t)(arow * 144 + q * 16);
        asm volatile("cp.async.cg.shared.global [%0], [%1], 16;" :: "r"(dst), "l"(src));
    }
    const __half* wbase = g_wsf + ((size_t)(sWs * 9 + tap) * 512 + blkoc * 64) * 512 + icc;
    #pragma unroll
    for (int r = 0; r < 2; r++) {
        int idx = tid + r * 256;
        int brow = idx >> 3, q = idx & 7;
        const __half* src = wbase + ((size_t)brow << 9) + q * 8;
        uint32_t dst = dstbase + (uint32_t)(18432 + brow * 144 + q * 16);
        asm volatile("cp.async.cg.shared.global [%0], [%1], 16;" :: "r"(dst), "l"(src));
    }
}

__global__ __launch_bounds__(256, 1) void conv_mma_k(const float* __restrict__ bias) {
    extern __shared__ float dyn[];
    float* sBias = dyn;                       // 64 used (128 reserved)
    char* sStage = (char*)(dyn + 128);        // 2 stages of 27648B
    float* sMaster = dyn + MASTER_OFF_F;      // [e*256 + tid], 32 per thread
    uint32_t bufu = smem_u32(sStage);
    int tid = threadIdx.x, lane = tid & 31, warp = tid >> 5;
    int g = lane >> 2, tig = lane & 3;
    int warpm = warp & 3, warpn = warp >> 2;  // 4 x 2
    int blkpx = blockIdx.x, blkoc = blockIdx.y, n = blockIdx.z;
    if (tid < 64) sBias[tid] = bias[blkoc * 64 + tid];

    float work[2][4][4] = {};

    conv_issue(0, bufu, tid, blkpx, blkoc, n);
    asm volatile("cp.async.commit_group;" ::: "memory");

    for (int iter = 0; iter < 216; iter++) {
        asm volatile("cp.async.wait_group 0;" ::: "memory");
        __syncthreads();
        if (iter + 1 < 216) {
            conv_issue(iter + 1, bufu + (uint32_t)((iter + 1) & 1) * STAGE_BYTES,
                       tid, blkpx, blkoc, n);
            asm volatile("cp.async.commit_group;" ::: "memory");
        }
        const uint32_t* sA = (const uint32_t*)(sStage + (iter & 1) * STAGE_BYTES);
        const uint32_t* sB = sA + 4608;   // +18432 bytes

        #pragma unroll
        for (int ks = 0; ks < 4; ks++) {
            int kw = ks * 8;
            uint32_t a[2][4];
            #pragma unroll
            for (int mt = 0; mt < 2; mt++) {
                int base = warpm * 32 + mt * 16;
                a[mt][0] = sA[(base + g) * 36 + kw + tig];
                a[mt][1] = sA[(base + g + 8) * 36 + kw + tig];
                a[mt][2] = sA[(base + g) * 36 + kw + 4 + tig];
                a[mt][3] = sA[(base + g + 8) * 36 + kw + 4 + tig];
            }
            #pragma unroll
            for (int nt = 0; nt < 4; nt++) {
                int col = warpn * 32 + nt * 8 + g;
                uint32_t b0 = sB[col * 36 + kw + tig];
                uint32_t b1 = sB[col * 36 + kw + 4 + tig];
                #pragma unroll
                for (int mt = 0; mt < 2; mt++) {
                    asm volatile(
                        "mma.sync.aligned.m16n8k16.row.col.f32.f16.f16.f32 "
                        "{%0,%1,%2,%3}, {%4,%5,%6,%7}, {%8,%9}, {%0,%1,%2,%3};"
                        : "+f"(work[mt][nt][0]), "+f"(work[mt][nt][1]),
                          "+f"(work[mt][nt][2]), "+f"(work[mt][nt][3])
                        : "r"(a[mt][0]), "r"(a[mt][1]), "r"(a[mt][2]), "r"(a[mt][3]),
                          "r"(b0), "r"(b1));
                }
            }
        }
        // flush every 4 iters (K-chain <= 256); corrections scaled 2^-12
        if ((iter & 3) == 3) {
            bool first = (iter == 3);
            bool corr = (iter >= 72);
            float sc = corr ? (1.f / 4096.f) : 1.f;
            #pragma unroll
            for (int mt = 0; mt < 2; mt++)
                #pragma unroll
                for (int nt = 0; nt < 4; nt++)
                    #pragma unroll
                    for (int q = 0; q < 4; q++) {
                        int e = ((mt * 4) + nt) * 4 + q;
                        float w = work[mt][nt][q] * sc;
                        if (first) sMaster[e * 256 + tid] = w;
                        else       sMaster[e * 256 + tid] += w;
                        work[mt][nt][q] = 0.f;
                    }
        }
    }
    __syncthreads();

    #pragma unroll
    for (int mt = 0; mt < 2; mt++) {
        int px = blkpx * 128 + warpm * 32 + mt * 16 + g;
        #pragma unroll
        for (int nt = 0; nt < 4; nt++) {
            int ocl = warpn * 32 + nt * 8 + 2 * tig;
            int oc = blkoc * 64 + ocl;
            float b0f = sBias[ocl], b1f = sBias[ocl + 1];
            size_t base0 = ((size_t)(n * CIN + oc) << 12);
            size_t base1 = ((size_t)(n * CIN + oc + 1) << 12);
            int e = ((mt * 4) + nt) * 4;
            g_h[base0 + px]     = fmaxf(sMaster[(e + 0) * 256 + tid] + b0f, 0.f);
            g_h[base1 + px]     = fmaxf(sMaster[(e + 1) * 256 + tid] + b1f, 0.f);
            g_h[base0 + px + 8] = fmaxf(sMaster[(e + 2) * 256 + tid] + b0f, 0.f);
            g_h[base1 + px + 8] = fmaxf(sMaster[(e + 3) * 256 + tid] + b1f, 0.f);
        }
    }
}

// ---------------- fused 1x1 heads + fg softmax ----------------
__global__ __launch_bounds__(256) void heads_k(const float* __restrict__ Wl,
                                               const float* __restrict__ bl,
                                               const float* __restrict__ Ws,
                                               const float* __restrict__ bs,
                                               float* __restrict__ dout) {
    int n = blockIdx.y;
    int p0 = blockIdx.x * 64;
    int tid = threadIdx.x;
    int pxg = tid & 15, cg = tid >> 4;
    int px0 = pxg * 4, c0 = cg * 4;

    __shared__ float sH[64][64];
    __shared__ float sWc[64][64];

    float acc[4][4] = {};

    for (int icc = 0; icc < CIN; icc += 64) {
        for (int idx = tid; idx < 4096; idx += 256) {
            int ic = idx >> 6, p = idx & 63;
            sH[ic][p] = g_h[(size_t)(n * CIN + icc + ic) * HWPIX + p0 + p];
        }
        for (int idx = tid; idx < 4096; idx += 256) {
            int ic = idx >> 6, c = idx & 63;
            float w = 0.f;
            if (c < 36)      w = Wl[(size_t)c * CIN + icc + ic];
            else if (c < 54) w = Ws[(size_t)(c - 36) * CIN + icc + ic];
            sWc[ic][c] = w;
        }
        __syncthreads();
        #pragma unroll 16
        for (int ic = 0; ic < 64; ic++) {
            float w0 = sWc[ic][c0 + 0], w1 = sWc[ic][c0 + 1];
            float w2 = sWc[ic][c0 + 2], w3 = sWc[ic][c0 + 3];
            float v0 = sH[ic][px0 + 0], v1 = sH[ic][px0 + 1];
            float v2 = sH[ic][px0 + 2], v3 = sH[ic][px0 + 3];
            acc[0][0] += w0 * v0; acc[0][1] += w0 * v1; acc[0][2] += w0 * v2; acc[0][3] += w0 * v3;
            acc[1][0] += w1 * v0; acc[1][1] += w1 * v1; acc[1][2] += w1 * v2; acc[1][3] += w1 * v3;
            acc[2][0] += w2 * v0; acc[2][1] += w2 * v1; acc[2][2] += w2 * v2; acc[2][3] += w2 * v3;
            acc[3][0] += w3 * v0; acc[3][1] += w3 * v1; acc[3][2] += w3 * v2; acc[3][3] += w3 * v3;
        }
        __syncthreads();
    }

    float val[4][4];
    #pragma unroll
    for (int ci = 0; ci < 4; ci++) {
        int cc = c0 + ci;
        float bv = (cc < 36) ? bl[cc] : ((cc < 54) ? bs[cc - 36] : 0.f);
        #pragma unroll
        for (int pi = 0; pi < 4; pi++) val[ci][pi] = acc[ci][pi] + bv;
    }
    #pragma unroll
    for (int ci = 0; ci < 4; ci++) {
        int cc = c0 + ci;
        #pragma unroll
        for (int pi = 0; pi < 4; pi++) {
            int p = p0 + px0 + pi;
            if (cc < 36)
                dout[LOCS_OFF + (size_t)n * 147456 + (size_t)p * 36 + cc] = val[ci][pi];
            else if (cc < 54)
                dout[SCORES_OFF + (size_t)n * 73728 + (size_t)p * 18 + (cc - 36)] = val[ci][pi];
        }
    }
    if (c0 >= 36 && c0 < 54) {
        #pragma unroll
        for (int pr = 0; pr < 2; pr++) {
            int ce = c0 + 2 * pr;
            if (ce + 1 < 54) {
                int a = (ce - 36) >> 1;
                #pragma unroll
                for (int pi = 0; pi < 4; pi++) {
                    float d = val[2 * pr + 1][pi] - val[2 * pr][pi];
                    float fg = 1.f / (1.f + expf(-d));
                    g_fg[n * NA + (p0 + px0 + pi) * 9 + a] = fg;
                }
            }
        }
    }
}

// ---------------- anchors ----------------
__global__ void anchors_k(float* __restrict__ dout) {
    int j = blockIdx.x * 256 + threadIdx.x;
    if (j >= NA) return;
    int p = j / 9, a = j % 9;
    int y = p >> 6, xx = p & 63;
    float ab[4];
    anchor_base(a, ab);
    float* o = dout + ANCH_OFF + (size_t)j * 4;
    o[0] = y * 16.f + ab[0];
    o[1] = xx * 16.f + ab[1];
    o[2] = y * 16.f + ab[2];
    o[3] = xx * 16.f + ab[3];
}

// ---------------- loc2bbox + clip + min-size + key ----------------
__global__ void boxes_k(const float* __restrict__ dout,
                        const int* __restrict__ pih, const int* __restrict__ piw) {
    int idx = blockIdx.x * 256 + threadIdx.x;
    if (idx >= N_BATCH * NA) return;
    int n = idx / NA, j = idx - n * NA;
    int p = j / 9, a = j - p * 9;
    int y = p >> 6, xx = p & 63;
    float ab[4];
    anchor_base(a, ab);
    float a0 = y * 16.f + ab[0], a1 = xx * 16.f + ab[1];
    float a2 = y * 16.f + ab[2], a3 = xx * 16.f + ab[3];

    const float* loc = dout + LOCS_OFF + (size_t)n * 147456 + (size_t)j * 4;
    float dy = loc[0], dx = loc[1], dh = loc[2], dw = loc[3];

    float src_h = a2 - a0, src_w = a3 - a1;
    float ctr_y = a0 + 0.5f * src_h, ctr_x = a1 + 0.5f * src_w;
    float cy = dy * src_h + ctr_y;
    float cx = dx * src_w + ctr_x;
    float hh = expf(dh) * src_h;
    float ww = expf(dw) * src_w;

    float fh = (float)(*pih), fw = (float)(*piw);
    float y1 = fminf(fmaxf(cy - 0.5f * hh, 0.f), fh);
    float y2 = fminf(fmaxf(cy + 0.5f * hh, 0.f), fh);
    float x1 = fminf(fmaxf(cx - 0.5f * ww, 0.f), fw);
    float x2 = fminf(fmaxf(cx + 0.5f * ww, 0.f), fw);

    bool valid = ((y2 - y1) >= 16.f) && ((x2 - x1) >= 16.f);
    float sc = valid ? g_fg[idx] : -INFINITY;

    g_boxes[idx] = make_float4(y1, x1, y2, x2);
    g_keys[idx] = f2key(sc);
}

// ---------------- radix select ----------------
__global__ __launch_bounds__(1024) void select_k() {
    int n = blockIdx.x;
    const unsigned* keys = g_keys + (size_t)n * NA;
    __shared__ unsigned hist[256];
    __shared__ unsigned sprefix;
    __shared__ int srem;
    if (threadIdx.x == 0) { sprefix = 0u; srem = NPRE; }
    __syncthreads();
    for (int pass = 0; pass < 4; pass++) {
        for (int b = threadIdx.x; b < 256; b += 1024) hist[b] = 0u;
        __syncthreads();
        int shift = 24 - 8 * pass;
        unsigned maskhi = pass ? (0xFFFFFFFFu << (32 - 8 * pass)) : 0u;
        unsigned pref = sprefix;
        for (int i = threadIdx.x; i < NA; i += 1024) {
            unsigned k = keys[i];
            if ((k & maskhi) == pref) atomicAdd(&hist[(k >> shift) & 0xFF], 1u);
        }
        __syncthreads();
        if (threadIdx.x == 0) {
            unsigned cum = 0;
            int rem = srem;
            for (int b = 255; b >= 0; b--) {
                cum += hist[b];
                if ((int)cum >= rem) {
                    srem = rem - (int)(cum - hist[b]);
                    sprefix = pref | ((unsigned)b << shift);
                    break;
                }
            }
        }
        __syncthreads();
    }
    if (threadIdx.x == 0) g_cut[n] = sprefix;
}

// ---------------- compact ----------------
__global__ void compact_k() {
    int idx = blockIdx.x * 256 + threadIdx.x;
    if (idx >= N_BATCH * NA) return;
    int n = idx / NA;
    unsigned k = g_keys[idx];
    if (k >= g_cut[n]) {
        int pos = atomicAdd(&g_cnt[n], 1);
        if (pos < SORTN) {
            unsigned j = (unsigned)(idx - n * NA);
            g_sel[n][pos] = ((unsigned long long)k << 32) | (0xFFFFFFFFu - j);
        }
    }
}

// ---------------- bitonic sort + gather ----------------
__global__ __launch_bounds__(1024) void sort_k() {
    int n = blockIdx.x;
    extern __shared__ unsigned long long sh[];
    for (int i = threadIdx.x; i < SORTN; i += 1024) sh[i] = g_sel[n][i];
    __syncthreads();
    for (int k = 2; k <= SORTN; k <<= 1) {
        for (int j = k >> 1; j > 0; j >>= 1) {
            for (int i = threadIdx.x; i < SORTN; i += 1024) {
                int ixj = i ^ j;
                if (ixj > i) {
                    unsigned long long a = sh[i], b = sh[ixj];
                    bool up = (i & k) == 0;
                    if (up ? (a < b) : (a > b)) { sh[i] = b; sh[ixj] = a; }
                }
            }
            __syncthreads();
        }
    }
    for (int r = threadIdx.x; r < NPRE; r += 1024) {
        unsigned long long comp = sh[r];
        unsigned j = 0xFFFFFFFFu - (unsigned)(comp & 0xFFFFFFFFull);
        if (j >= NA) j = NA - 1;
        g_bsort[n][r] = g_boxes[(size_t)n * NA + j];
    }
}

// ---------------- NMS masks ----------------
__global__ __launch_bounds__(64) void masks_k() {
    int n = blockIdx.z, ci = blockIdx.y, cj = blockIdx.x;
    int t = threadIdx.x;
    int i = ci * 64 + t;
    if (cj < ci) { g_masks[n][i][cj] = 0ull; return; }
    __shared__ float4 bj[64];
    int jg = cj * 64 + t;
    bj[t] = (jg < NPRE) ? g_bsort[n][jg] : make_float4(0.f, 0.f, 0.f, 0.f);
    __syncthreads();
    if (i >= NPRE) { g_masks[n][i][cj] = 0ull; return; }
    float4 bi = g_bsort[n][i];
    float areai = (bi.z - bi.x) * (bi.w - bi.y);
    unsigned long long m = 0ull;
    int jbase = cj * 64;
    #pragma unroll 8
    for (int jj = 0; jj < 64; jj++) {
        int jgl = jbase + jj;
        if (jgl > i && jgl < NPRE) {
            float4 bb = bj[jj];
            float ty1 = fmaxf(bi.x, bb.x), tx1 = fmaxf(bi.y, bb.y);
            float ty2 = fminf(bi.z, bb.z), tx2 = fminf(bi.w, bb.w);
            float ihh = fmaxf(ty2 - ty1, 0.f), iww = fmaxf(tx2 - tx1, 0.f);
            float inter = ihh * iww;
            float areaj = (bb.z - bb.x) * (bb.w - bb.y);
            float iou = inter / (areai + areaj - inter + 1e-10f);
            if (iou > 0.7f) m |= (1ull << jj);
        }
    }
    g_masks[n][i][cj] = m;
}

// ---------------- single-warp NMS reduction (broadcast-word chain) + emit ----------------
__global__ __launch_bounds__(32) void nms_emit_k(float* __restrict__ dout) {
    int n = blockIdx.x;
    int l = threadIdx.x;
    int c0 = l, c1 = l + 32, c2 = l + 64;
    bool v2 = c2 < NCHUNK;
    unsigned long long rv0 = 0, rv1 = 0, rv2 = 0;
    unsigned long long b0[8], b1[8], b2[8], mb[8];
    #pragma unroll
    for (int s = 0; s < 8; s++) {
        b0[s] = g_masks[n][s][c0];
        b1[s] = g_masks[n][s][c1];
        b2[s] = v2 ? g_masks[n][s][c2] : 0ull;
        mb[s] = g_masks[n][s][0];            // rows 0..7 are in chunk 0
    }
    unsigned long long cur = 0ull;           // local replica of remv[current chunk]
    for (int ib = 0; ib < NPRE; ib += 8) {
        #pragma unroll
        for (int s = 0; s < 8; s++) {
            int i = ib + s;
            unsigned long long cm0 = b0[s], cm1 = b1[s], cm2 = b2[s], m = mb[s];
            if (i + 8 < NPRE) {
                b0[s] = g_masks[n][i + 8][c0];
                b1[s] = g_masks[n][i + 8][c1];
                b2[s] = v2 ? g_masks[n][i + 8][c2] : 0ull;
                mb[s] = g_masks[n][i + 8][(i + 8) >> 6];   // uniform addr -> broadcast load
            }
            if ((i & 63) == 0) {
                int ch = i >> 6, slot = ch >> 5, src = ch & 31;
                unsigned long long rsel = (slot == 0) ? rv0 : ((slot == 1) ? rv1 : rv2);
                cur = __shfl_sync(0xFFFFFFFFu, rsel, src);
            }
            if (!((cur >> (i & 63)) & 1ull)) {
                rv0 |= cm0; rv1 |= cm1; rv2 |= cm2;
                cur |= m;
            }
        }
    }
    __shared__ unsigned long long remv[96];
    remv[l] = rv0; remv[l + 32] = rv1;
    if (v2) remv[l + 64] = rv2;
    __syncwarp();
    float* rind = dout + RIND_OFF + n * NPOST;
    for (int q = l; q < NPOST; q += 32) rind[q] = (float)n;
    if (l == 0) {
        float4* rois = (float4*)(dout + ROIS_OFF) + n * NPOST;
        int r = 0;
        for (int i = 0; i < NPRE && r < NPOST; i++)
            if (((remv[i >> 6] >> (i & 63)) & 1ull) == 0ull) rois[r++] = g_bsort[n][i];
        for (int i = 0; i < NPRE && r < NPOST; i++)
            if (((remv[i >> 6] >> (i & 63)) & 1ull) != 0ull) rois[r++] = g_bsort[n][i];
    }
}

// ---------------- launch ----------------
extern "C" void kernel_launch(void* const* d_in, const int* in_sizes, int n_in,
                              void* d_out, int out_size) {
    const float* x  = (const float*)d_in[0];
    const float* W1 = (const float*)d_in[1];
    const float* b1 = (const float*)d_in[2];
    const float* Ws = (const float*)d_in[3];
    const float* bs = (const float*)d_in[4];
    const float* Wl = (const float*)d_in[5];
    const float* bl = (const float*)d_in[6];
    const int* ih   = (const int*)d_in[7];
    const int* iw   = (const int*)d_in[8];
    float* out = (float*)d_out;

    cudaFuncSetAttribute(sort_k, cudaFuncAttributeMaxDynamicSharedMemorySize, SORTN * 8);
    cudaFuncSetAttribute(conv_mma_k, cudaFuncAttributeMaxDynamicSharedMemorySize, CONV_SMEM);

    init_k<<<(N_BATCH * SORTN + 255) / 256, 256>>>();
    xzero_k<<<(int)(((size_t)N_BATCH * 2 * PADPX * CIN / 4 + 255) / 256), 256>>>();
    wsplit_k<<<(9 * CIN * CIN + 255) / 256, 256>>>(W1);
    xsplit_k<<<dim3(64, 8, 4), 256>>>(x);
    conv_mma_k<<<dim3(32, 8, 4), 256, CONV_SMEM>>>(b1);
    heads_k<<<dim3(64, 4), 256>>>(Wl, bl, Ws, bs, out);
    anchors_k<<<(NA + 255) / 256, 256>>>(out);
    boxes_k<<<(N_BATCH * NA + 255) / 256, 256>>>(out, ih, iw);
    select_k<<<N_BATCH, 1024>>>();
    compact_k<<<(N_BATCH * NA + 255) / 256, 256>>>();
    sort_k<<<N_BATCH, 1024, SORTN * 8>>>();
    masks_k<<<dim3(NCHUNK, NCHUNK, N_BATCH), 64>>>();
    nms_emit_k<<<N_BATCH, 32>>>(out);
}

// round 11
// speedup vs baseline: 1.0616x; 1.0616x over previous
#include <cuda_runtime.h>
#include <cuda_fp16.h>
#include <math.h>
#include <stdint.h>

#define N_BATCH 4
#define CIN     512
#define HWPIX   4096
#define NA      36864
#define NPRE    6000
#define NPOST   300
#define NCHUNK  94
#define NPAD    6016
#define SORTN   8192
#define PADPX   4356      // 66*66

#define LOCS_OFF   0
#define SCORES_OFF 589824
#define ROIS_OFF   884736
#define RIND_OFF   889536
#define ANCH_OFF   890736

// conv smem: 128 bias floats + 2 stages of (A 128x72 + B 128x72 halves) + master 64x256 floats
#define STAGE_BYTES  36864                      // 2 * 128 * 144
#define MASTER_OFF_F (128 + 2 * STAGE_BYTES / 4)
#define CONV_SMEM    (512 + 2 * STAGE_BYTES + 65536)

// ---------------- scratch ----------------
__device__ float               g_h[N_BATCH * CIN * HWPIX];
__device__ __half              g_xs[(size_t)N_BATCH * 2 * PADPX * CIN];   // fp16 hi / lo*4096
__device__ __half              g_wsf[(size_t)2 * 9 * CIN * CIN];
__device__ float               g_fg[N_BATCH * NA];
__device__ float4              g_boxes[N_BATCH * NA];
__device__ unsigned            g_keys[N_BATCH * NA];
__device__ unsigned            g_cut[N_BATCH];
__device__ int                 g_cnt[N_BATCH];
__device__ unsigned long long  g_sel[N_BATCH][SORTN];
__device__ float4              g_bsort[N_BATCH][NPAD];
__device__ unsigned long long  g_masks[N_BATCH][NPAD][NCHUNK];

// ---------------- helpers ----------------
__device__ __forceinline__ uint32_t smem_u32(const void* p) {
    uint32_t a;
    asm("{ .reg .u64 t; cvta.to.shared.u64 t, %1; cvt.u32.u64 %0, t; }" : "=r"(a) : "l"(p));
    return a;
}
__device__ __forceinline__ unsigned f2key(float f) {
    unsigned u = __float_as_uint(f);
    return (u & 0x80000000u) ? ~u : (u | 0x80000000u);
}
__device__ __forceinline__ void anchor_base(int a, float* out) {
    const double ratios[3] = {0.5, 1.0, 2.0};
    const double scales[3] = {8.0, 16.0, 32.0};
    int ri = a / 3, si = a % 3;
    double h = 16.0 * scales[si] * sqrt(ratios[ri]);
    double w = 16.0 * scales[si] * sqrt(1.0 / ratios[ri]);
    out[0] = (float)(8.0 - h * 0.5);
    out[1] = (float)(8.0 - w * 0.5);
    out[2] = (float)(8.0 + h * 0.5);
    out[3] = (float)(8.0 + w * 0.5);
}

// ---------------- init ----------------
__global__ void init_k() {
    int idx = blockIdx.x * 256 + threadIdx.x;
    if (idx < N_BATCH) g_cnt[idx] = 0;
    if (idx < N_BATCH * SORTN) (&g_sel[0][0])[idx] = 0ull;
}

__global__ void xzero_k() {
    size_t idx = (size_t)blockIdx.x * 256 + threadIdx.x;
    size_t total = (size_t)N_BATCH * 2 * PADPX * CIN / 4;  // u64 chunks of halves
    if (idx < total) ((unsigned long long*)g_xs)[idx] = 0ull;
}

// split W1 -> g_wsf[s][tap][oc][ic]  (fp16 hi, lo*4096)
__global__ void wsplit_k(const float* __restrict__ W1) {
    int e = blockIdx.x * 256 + threadIdx.x;
    if (e >= 9 * CIN * CIN) return;
    int t = e / (CIN * CIN);
    int oi = e - t * (CIN * CIN);
    int oc = oi >> 9, ic = oi & 511;
    float w = W1[((size_t)oc * CIN + ic) * 9 + t];
    __half hi = __float2half(w);
    float lo = (w - __half2float(hi)) * 4096.f;
    size_t o = ((size_t)t * CIN + oc) * CIN + ic;
    g_wsf[o] = hi;
    g_wsf[o + (size_t)9 * CIN * CIN] = __float2half(lo);
}

// transpose + split x -> g_xs[n][s][prow*66+pcol][ic], interior at +1 offset
__global__ __launch_bounds__(256) void xsplit_k(const float* __restrict__ x) {
    __shared__ float s[64][65];
    int row = blockIdx.x, ic0 = blockIdx.y * 64, n = blockIdx.z;
    int tid = threadIdx.x;
    #pragma unroll
    for (int k = 0; k < 16; k++) {
        int idx = tid + k * 256;
        int ic_l = idx >> 6, p = idx & 63;
        s[ic_l][p] = x[((size_t)(n * CIN + ic0 + ic_l) << 12) + row * 64 + p];
    }
    __syncthreads();
    #pragma unroll
    for (int k = 0; k < 16; k++) {
        int idx = tid + k * 256;
        int p = idx >> 6, ic_l = idx & 63;
        float v = s[ic_l][p];
        __half hi = __float2half(v);
        float lo = (v - __half2float(hi)) * 4096.f;
        int prow = (row + 1) * 66 + (p + 1);
        size_t b = ((size_t)(n * 2) * PADPX + prow) * CIN + ic0 + ic_l;
        g_xs[b] = hi;
        g_xs[b + (size_t)PADPX * CIN] = __float2half(lo);
    }
}

// ---------------- conv3x3 via mma.sync fp16 3-term (scaled limbs), chunked accumulation ----------------
// grid (32 px-tiles, 4 oc-blocks, 4 n) = 512 CTAs, 256 threads (8 warps: 4m x 2n).
// Block tile 128px x 128oc; K=64 ic per iter; 216 iters: 72 hh + 72 hi*lo + 72 lo*hi.
// Work acc flushed to smem master every 4 iters (in-MMA K-chain <= 256); corr flushes scaled 2^-12.
__device__ __forceinline__ void conv_issue(int iter, uint32_t dstbase,
                                           int tid, int blkpx, int blkoc, int n) {
    int ph = iter / 72;
    int rem = iter - ph * 72;
    int tap = rem >> 3;
    int icc = (rem & 7) * 64;
    int ky = tap / 3, kx = tap - ky * 3;
    int sAs = (ph == 2) ? 1 : 0;
    int sWs = (ph == 1) ? 1 : 0;
    const __half* xbase = g_xs + (((size_t)(n * 2 + sAs)) * PADPX << 9) + icc;
    #pragma unroll
    for (int r = 0; r < 4; r++) {
        int idx = tid + r * 256;
        int arow = idx >> 3, q = idx & 7;
        int p = blkpx * 128 + arow;
        int ppix = ((p >> 6) + ky) * 66 + (p & 63) + kx;
        const __half* src = xbase + ((size_t)ppix << 9) + q * 8;
        uint32_t dst = dstbase + (uint32_t)(arow * 144 + q * 16);
        asm volatile("cp.async.cg.shared.global [%0], [%1], 16;" :: "r"(dst), "l"(src));
    }
    const __half* wbase = g_wsf + ((size_t)(sWs * 9 + tap) * 512 + blkoc * 128) * 512 + icc;
    #pragma unroll
    for (int r = 0; r < 4; r++) {
        int idx = tid + r * 256;
        int brow = idx >> 3, q = idx & 7;
        const __half* src = wbase + ((size_t)brow << 9) + q * 8;
        uint32_t dst = dstbase + (uint32_t)(18432 + brow * 144 + q * 16);
        asm volatile("cp.async.cg.shared.global [%0], [%1], 16;" :: "r"(dst), "l"(src));
    }
}

__global__ __launch_bounds__(256, 1) void conv_mma_k(const float* __restrict__ bias) {
    extern __shared__ float dyn[];
    float* sBias = dyn;                       // 128
    char* sStage = (char*)(dyn + 128);        // 2 stages of 36864B
    float* sMaster = dyn + MASTER_OFF_F;      // [e*256 + tid], 64 per thread
    uint32_t bufu = smem_u32(sStage);
    int tid = threadIdx.x, lane = tid & 31, warp = tid >> 5;
    int g = lane >> 2, tig = lane & 3;
    int warpm = warp & 3, warpn = warp >> 2;  // 4 x 2
    int blkpx = blockIdx.x, blkoc = blockIdx.y, n = blockIdx.z;
    if (tid < 128) sBias[tid] = bias[blkoc * 128 + tid];

    float work[2][8][4] = {};

    conv_issue(0, bufu, tid, blkpx, blkoc, n);
    asm volatile("cp.async.commit_group;" ::: "memory");

    for (int iter = 0; iter < 216; iter++) {
        asm volatile("cp.async.wait_group 0;" ::: "memory");
        __syncthreads();
        if (iter + 1 < 216) {
            conv_issue(iter + 1, bufu + (uint32_t)((iter + 1) & 1) * STAGE_BYTES,
                       tid, blkpx, blkoc, n);
            asm volatile("cp.async.commit_group;" ::: "memory");
        }
        const uint32_t* sA = (const uint32_t*)(sStage + (iter & 1) * STAGE_BYTES);
        const uint32_t* sB = sA + 4608;   // +18432 bytes

        #pragma unroll
        for (int ks = 0; ks < 4; ks++) {
            int kw = ks * 8;   // u32 offset of k-block
            uint32_t a[2][4];
            #pragma unroll
            for (int mt = 0; mt < 2; mt++) {
                int base = warpm * 32 + mt * 16;
                a[mt][0] = sA[(base + g) * 36 + kw + tig];
                a[mt][1] = sA[(base + g + 8) * 36 + kw + tig];
                a[mt][2] = sA[(base + g) * 36 + kw + 4 + tig];
                a[mt][3] = sA[(base + g + 8) * 36 + kw + 4 + tig];
            }
            #pragma unroll
            for (int nt = 0; nt < 8; nt++) {
                int col = warpn * 64 + nt * 8 + g;
                uint32_t b0 = sB[col * 36 + kw + tig];
                uint32_t b1 = sB[col * 36 + kw + 4 + tig];
                #pragma unroll
                for (int mt = 0; mt < 2; mt++) {
                    asm volatile(
                        "mma.sync.aligned.m16n8k16.row.col.f32.f16.f16.f32 "
                        "{%0,%1,%2,%3}, {%4,%5,%6,%7}, {%8,%9}, {%0,%1,%2,%3};"
                        : "+f"(work[mt][nt][0]), "+f"(work[mt][nt][1]),
                          "+f"(work[mt][nt][2]), "+f"(work[mt][nt][3])
                        : "r"(a[mt][0]), "r"(a[mt][1]), "r"(a[mt][2]), "r"(a[mt][3]),
                          "r"(b0), "r"(b1));
                }
            }
        }
        // flush every 4 iters (K-chain <= 256); corrections scaled 2^-12
        if ((iter & 3) == 3) {
            bool first = (iter == 3);
            bool corr = (iter >= 72);
            float sc = corr ? (1.f / 4096.f) : 1.f;
            #pragma unroll
            for (int mt = 0; mt < 2; mt++)
                #pragma unroll
                for (int nt = 0; nt < 8; nt++)
                    #pragma unroll
                    for (int q = 0; q < 4; q++) {
                        int e = ((mt * 8) + nt) * 4 + q;
                        float w = work[mt][nt][q] * sc;
                        if (first) sMaster[e * 256 + tid] = w;
                        else       sMaster[e * 256 + tid] += w;
                        work[mt][nt][q] = 0.f;
                    }
        }
    }
    __syncthreads();

    #pragma unroll
    for (int mt = 0; mt < 2; mt++) {
        int px = blkpx * 128 + warpm * 32 + mt * 16 + g;
        #pragma unroll
        for (int nt = 0; nt < 8; nt++) {
            int ocl = warpn * 64 + nt * 8 + 2 * tig;
            int oc = blkoc * 128 + ocl;
            float b0f = sBias[ocl], b1f = sBias[ocl + 1];
            size_t base0 = ((size_t)(n * CIN + oc) << 12);
            size_t base1 = ((size_t)(n * CIN + oc + 1) << 12);
            int e = ((mt * 8) + nt) * 4;
            g_h[base0 + px]     = fmaxf(sMaster[(e + 0) * 256 + tid] + b0f, 0.f);
            g_h[base1 + px]     = fmaxf(sMaster[(e + 1) * 256 + tid] + b1f, 0.f);
            g_h[base0 + px + 8] = fmaxf(sMaster[(e + 2) * 256 + tid] + b0f, 0.f);
            g_h[base1 + px + 8] = fmaxf(sMaster[(e + 3) * 256 + tid] + b1f, 0.f);
        }
    }
}

// ---------------- fused 1x1 heads + fg softmax ----------------
__global__ __launch_bounds__(256) void heads_k(const float* __restrict__ Wl,
                                               const float* __restrict__ bl,
                                               const float* __restrict__ Ws,
                                               const float* __restrict__ bs,
                                               float* __restrict__ dout) {
    int n = blockIdx.y;
    int p0 = blockIdx.x * 64;
    int tid = threadIdx.x;
    int pxg = tid & 15, cg = tid >> 4;
    int px0 = pxg * 4, c0 = cg * 4;

    __shared__ float sH[64][64];
    __shared__ float sWc[64][64];

    float acc[4][4] = {};

    for (int icc = 0; icc < CIN; icc += 64) {
        for (int idx = tid; idx < 4096; idx += 256) {
            int ic = idx >> 6, p = idx & 63;
            sH[ic][p] = g_h[(size_t)(n * CIN + icc + ic) * HWPIX + p0 + p];
        }
        for (int idx = tid; idx < 4096; idx += 256) {
            int ic = idx >> 6, c = idx & 63;
            float w = 0.f;
            if (c < 36)      w = Wl[(size_t)c * CIN + icc + ic];
            else if (c < 54) w = Ws[(size_t)(c - 36) * CIN + icc + ic];
            sWc[ic][c] = w;
        }
        __syncthreads();
        #pragma unroll 16
        for (int ic = 0; ic < 64; ic++) {
            float w0 = sWc[ic][c0 + 0], w1 = sWc[ic][c0 + 1];
            float w2 = sWc[ic][c0 + 2], w3 = sWc[ic][c0 + 3];
            float v0 = sH[ic][px0 + 0], v1 = sH[ic][px0 + 1];
            float v2 = sH[ic][px0 + 2], v3 = sH[ic][px0 + 3];
            acc[0][0] += w0 * v0; acc[0][1] += w0 * v1; acc[0][2] += w0 * v2; acc[0][3] += w0 * v3;
            acc[1][0] += w1 * v0; acc[1][1] += w1 * v1; acc[1][2] += w1 * v2; acc[1][3] += w1 * v3;
            acc[2][0] += w2 * v0; acc[2][1] += w2 * v1; acc[2][2] += w2 * v2; acc[2][3] += w2 * v3;
            acc[3][0] += w3 * v0; acc[3][1] += w3 * v1; acc[3][2] += w3 * v2; acc[3][3] += w3 * v3;
        }
        __syncthreads();
    }

    float val[4][4];
    #pragma unroll
    for (int ci = 0; ci < 4; ci++) {
        int cc = c0 + ci;
        float bv = (cc < 36) ? bl[cc] : ((cc < 54) ? bs[cc - 36] : 0.f);
        #pragma unroll
        for (int pi = 0; pi < 4; pi++) val[ci][pi] = acc[ci][pi] + bv;
    }
    #pragma unroll
    for (int ci = 0; ci < 4; ci++) {
        int cc = c0 + ci;
        #pragma unroll
        for (int pi = 0; pi < 4; pi++) {
            int p = p0 + px0 + pi;
            if (cc < 36)
                dout[LOCS_OFF + (size_t)n * 147456 + (size_t)p * 36 + cc] = val[ci][pi];
            else if (cc < 54)
                dout[SCORES_OFF + (size_t)n * 73728 + (size_t)p * 18 + (cc - 36)] = val[ci][pi];
        }
    }
    if (c0 >= 36 && c0 < 54) {
        #pragma unroll
        for (int pr = 0; pr < 2; pr++) {
            int ce = c0 + 2 * pr;
            if (ce + 1 < 54) {
                int a = (ce - 36) >> 1;
                #pragma unroll
                for (int pi = 0; pi < 4; pi++) {
                    float d = val[2 * pr + 1][pi] - val[2 * pr][pi];
                    float fg = 1.f / (1.f + expf(-d));
                    g_fg[n * NA + (p0 + px0 + pi) * 9 + a] = fg;
                }
            }
        }
    }
}

// ---------------- anchors ----------------
__global__ void anchors_k(float* __restrict__ dout) {
    int j = blockIdx.x * 256 + threadIdx.x;
    if (j >= NA) return;
    int p = j / 9, a = j % 9;
    int y = p >> 6, xx = p & 63;
    float ab[4];
    anchor_base(a, ab);
    float* o = dout + ANCH_OFF + (size_t)j * 4;
    o[0] = y * 16.f + ab[0];
    o[1] = xx * 16.f + ab[1];
    o[2] = y * 16.f + ab[2];
    o[3] = xx * 16.f + ab[3];
}

// ---------------- loc2bbox + clip + min-size + key ----------------
__global__ void boxes_k(const float* __restrict__ dout,
                        const int* __restrict__ pih, const int* __restrict__ piw) {
    int idx = blockIdx.x * 256 + threadIdx.x;
    if (idx >= N_BATCH * NA) return;
    int n = idx / NA, j = idx - n * NA;
    int p = j / 9, a = j - p * 9;
    int y = p >> 6, xx = p & 63;
    float ab[4];
    anchor_base(a, ab);
    float a0 = y * 16.f + ab[0], a1 = xx * 16.f + ab[1];
    float a2 = y * 16.f + ab[2], a3 = xx * 16.f + ab[3];

    const float* loc = dout + LOCS_OFF + (size_t)n * 147456 + (size_t)j * 4;
    float dy = loc[0], dx = loc[1], dh = loc[2], dw = loc[3];

    float src_h = a2 - a0, src_w = a3 - a1;
    float ctr_y = a0 + 0.5f * src_h, ctr_x = a1 + 0.5f * src_w;
    float cy = dy * src_h + ctr_y;
    float cx = dx * src_w + ctr_x;
    float hh = expf(dh) * src_h;
    float ww = expf(dw) * src_w;

    float fh = (float)(*pih), fw = (float)(*piw);
    float y1 = fminf(fmaxf(cy - 0.5f * hh, 0.f), fh);
    float y2 = fminf(fmaxf(cy + 0.5f * hh, 0.f), fh);
    float x1 = fminf(fmaxf(cx - 0.5f * ww, 0.f), fw);
    float x2 = fminf(fmaxf(cx + 0.5f * ww, 0.f), fw);

    bool valid = ((y2 - y1) >= 16.f) && ((x2 - x1) >= 16.f);
    float sc = valid ? g_fg[idx] : -INFINITY;

    g_boxes[idx] = make_float4(y1, x1, y2, x2);
    g_keys[idx] = f2key(sc);
}

// ---------------- radix select ----------------
__global__ __launch_bounds__(1024) void select_k() {
    int n = blockIdx.x;
    const unsigned* keys = g_keys + (size_t)n * NA;
    __shared__ unsigned hist[256];
    __shared__ unsigned sprefix;
    __shared__ int srem;
    if (threadIdx.x == 0) { sprefix = 0u; srem = NPRE; }
    __syncthreads();
    for (int pass = 0; pass < 4; pass++) {
        for (int b = threadIdx.x; b < 256; b += 1024) hist[b] = 0u;
        __syncthreads();
        int shift = 24 - 8 * pass;
        unsigned maskhi = pass ? (0xFFFFFFFFu << (32 - 8 * pass)) : 0u;
        unsigned pref = sprefix;
        for (int i = threadIdx.x; i < NA; i += 1024) {
            unsigned k = keys[i];
            if ((k & maskhi) == pref) atomicAdd(&hist[(k >> shift) & 0xFF], 1u);
        }
        __syncthreads();
        if (threadIdx.x == 0) {
            unsigned cum = 0;
            int rem = srem;
            for (int b = 255; b >= 0; b--) {
                cum += hist[b];
                if ((int)cum >= rem) {
                    srem = rem - (int)(cum - hist[b]);
                    sprefix = pref | ((unsigned)b << shift);
                    break;
                }
            }
        }
        __syncthreads();
    }
    if (threadIdx.x == 0) g_cut[n] = sprefix;
}

// ---------------- compact ----------------
__global__ void compact_k() {
    int idx = blockIdx.x * 256 + threadIdx.x;
    if (idx >= N_BATCH * NA) return;
    int n = idx / NA;
    unsigned k = g_keys[idx];
    if (k >= g_cut[n]) {
        int pos = atomicAdd(&g_cnt[n], 1);
        if (pos < SORTN) {
            unsigned j = (unsigned)(idx - n * NA);
            g_sel[n][pos] = ((unsigned long long)k << 32) | (0xFFFFFFFFu - j);
        }
    }
}

// ---------------- bitonic sort + gather ----------------
__global__ __launch_bounds__(1024) void sort_k() {
    int n = blockIdx.x;
    extern __shared__ unsigned long long sh[];
    for (int i = threadIdx.x; i < SORTN; i += 1024) sh[i] = g_sel[n][i];
    __syncthreads();
    for (int k = 2; k <= SORTN; k <<= 1) {
        for (int j = k >> 1; j > 0; j >>= 1) {
            for (int i = threadIdx.x; i < SORTN; i += 1024) {
                int ixj = i ^ j;
                if (ixj > i) {
                    unsigned long long a = sh[i], b = sh[ixj];
                    bool up = (i & k) == 0;
                    if (up ? (a < b) : (a > b)) { sh[i] = b; sh[ixj] = a; }
                }
            }
            __syncthreads();
        }
    }
    for (int r = threadIdx.x; r < NPRE; r += 1024) {
        unsigned long long comp = sh[r];
        unsigned j = 0xFFFFFFFFu - (unsigned)(comp & 0xFFFFFFFFull);
        if (j >= NA) j = NA - 1;
        g_bsort[n][r] = g_boxes[(size_t)n * NA + j];
    }
}

// ---------------- NMS masks ----------------
__global__ __launch_bounds__(64) void masks_k() {
    int n = blockIdx.z, ci = blockIdx.y, cj = blockIdx.x;
    int t = threadIdx.x;
    int i = ci * 64 + t;
    if (cj < ci) { g_masks[n][i][cj] = 0ull; return; }
    __shared__ float4 bj[64];
    int jg = cj * 64 + t;
    bj[t] = (jg < NPRE) ? g_bsort[n][jg] : make_float4(0.f, 0.f, 0.f, 0.f);
    __syncthreads();
    if (i >= NPRE) { g_masks[n][i][cj] = 0ull; return; }
    float4 bi = g_bsort[n][i];
    float areai = (bi.z - bi.x) * (bi.w - bi.y);
    unsigned long long m = 0ull;
    int jbase = cj * 64;
    #pragma unroll 8
    for (int jj = 0; jj < 64; jj++) {
        int jgl = jbase + jj;
        if (jgl > i && jgl < NPRE) {
            float4 bb = bj[jj];
            float ty1 = fmaxf(bi.x, bb.x), tx1 = fmaxf(bi.y, bb.y);
            float ty2 = fminf(bi.z, bb.z), tx2 = fminf(bi.w, bb.w);
            float ihh = fmaxf(ty2 - ty1, 0.f), iww = fmaxf(tx2 - tx1, 0.f);
            float inter = ihh * iww;
            float areaj = (bb.z - bb.x) * (bb.w - bb.y);
            float iou = inter / (areai + areaj - inter + 1e-10f);
            if (iou > 0.7f) m |= (1ull << jj);
        }
    }
    g_masks[n][i][cj] = m;
}

// ---------------- single-warp NMS reduction (broadcast-word chain) + emit ----------------
__global__ __launch_bounds__(32) void nms_emit_k(float* __restrict__ dout) {
    int n = blockIdx.x;
    int l = threadIdx.x;
    int c0 = l, c1 = l + 32, c2 = l + 64;
    bool v2 = c2 < NCHUNK;
    unsigned long long rv0 = 0, rv1 = 0, rv2 = 0;
    unsigned long long b0[8], b1[8], b2[8], mb[8];
    #pragma unroll
    for (int s = 0; s < 8; s++) {
        b0[s] = g_masks[n][s][c0];
        b1[s] = g_masks[n][s][c1];
        b2[s] = v2 ? g_masks[n][s][c2] : 0ull;
        mb[s] = g_masks[n][s][0];            // rows 0..7 are in chunk 0
    }
    unsigned long long cur = 0ull;           // local replica of remv[current chunk]
    for (int ib = 0; ib < NPRE; ib += 8) {
        #pragma unroll
        for (int s = 0; s < 8; s++) {
            int i = ib + s;
            unsigned long long cm0 = b0[s], cm1 = b1[s], cm2 = b2[s], m = mb[s];
            if (i + 8 < NPRE) {
                b0[s] = g_masks[n][i + 8][c0];
                b1[s] = g_masks[n][i + 8][c1];
                b2[s] = v2 ? g_masks[n][i + 8][c2] : 0ull;
                mb[s] = g_masks[n][i + 8][(i + 8) >> 6];   // uniform addr -> broadcast load
            }
            if ((i & 63) == 0) {
                int ch = i >> 6, slot = ch >> 5, src = ch & 31;
                unsigned long long rsel = (slot == 0) ? rv0 : ((slot == 1) ? rv1 : rv2);
                cur = __shfl_sync(0xFFFFFFFFu, rsel, src);
            }
            if (!((cur >> (i & 63)) & 1ull)) {
                rv0 |= cm0; rv1 |= cm1; rv2 |= cm2;
                cur |= m;
            }
        }
    }
    __shared__ unsigned long long remv[96];
    remv[l] = rv0; remv[l + 32] = rv1;
    if (v2) remv[l + 64] = rv2;
    __syncwarp();
    float* rind = dout + RIND_OFF + n * NPOST;
    for (int q = l; q < NPOST; q += 32) rind[q] = (float)n;
    if (l == 0) {
        float4* rois = (float4*)(dout + ROIS_OFF) + n * NPOST;
        int r = 0;
        for (int i = 0; i < NPRE && r < NPOST; i++)
            if (((remv[i >> 6] >> (i & 63)) & 1ull) == 0ull) rois[r++] = g_bsort[n][i];
        for (int i = 0; i < NPRE && r < NPOST; i++)
            if (((remv[i >> 6] >> (i & 63)) & 1ull) != 0ull) rois[r++] = g_bsort[n][i];
    }
}

// ---------------- launch ----------------
extern "C" void kernel_launch(void* const* d_in, const int* in_sizes, int n_in,
                              void* d_out, int out_size) {
    const float* x  = (const float*)d_in[0];
    const float* W1 = (const float*)d_in[1];
    const float* b1 = (const float*)d_in[2];
    const float* Ws = (const float*)d_in[3];
    const float* bs = (const float*)d_in[4];
    const float* Wl = (const float*)d_in[5];
    const float* bl = (const float*)d_in[6];
    const int* ih   = (const int*)d_in[7];
    const int* iw   = (const int*)d_in[8];
    float* out = (float*)d_out;

    cudaFuncSetAttribute(sort_k, cudaFuncAttributeMaxDynamicSharedMemorySize, SORTN * 8);
    cudaFuncSetAttribute(conv_mma_k, cudaFuncAttributeMaxDynamicSharedMemorySize, CONV_SMEM);

    init_k<<<(N_BATCH * SORTN + 255) / 256, 256>>>();
    xzero_k<<<(int)(((size_t)N_BATCH * 2 * PADPX * CIN / 4 + 255) / 256), 256>>>();
    wsplit_k<<<(9 * CIN * CIN + 255) / 256, 256>>>(W1);
    xsplit_k<<<dim3(64, 8, 4), 256>>>(x);
    conv_mma_k<<<dim3(32, 4, 4), 256, CONV_SMEM>>>(b1);
    heads_k<<<dim3(64, 4), 256>>>(Wl, bl, Ws, bs, out);
    anchors_k<<<(NA + 255) / 256, 256>>>(out);
    boxes_k<<<(N_BATCH * NA + 255) / 256, 256>>>(out, ih, iw);
    select_k<<<N_BATCH, 1024>>>();
    compact_k<<<(N_BATCH * NA + 255) / 256, 256>>>();
    sort_k<<<N_BATCH, 1024, SORTN * 8>>>();
    masks_k<<<dim3(NCHUNK, NCHUNK, N_BATCH), 64>>>();
    nms_emit_k<<<N_BATCH, 32>>>(out);
}

// round 12
// speedup vs baseline: 1.4966x; 1.4098x over previous
#include <cuda_runtime.h>
#include <cuda_fp16.h>
#include <math.h>
#include <stdint.h>

#define N_BATCH 4
#define CIN     512
#define HWPIX   4096
#define NA      36864
#define NPRE    6000
#define NPOST   300
#define NCHUNK  94
#define NPAD    6016
#define SORTN   8192
#define PADPX   4356      // 66*66

#define LOCS_OFF   0
#define SCORES_OFF 589824
#define ROIS_OFF   884736
#define RIND_OFF   889536
#define ANCH_OFF   890736

// conv smem: 128 bias floats + 2 stages of (A 128x72 + B 128x72 halves) + master 64x256 floats
#define STAGE_BYTES  36864                      // 2 * 128 * 144
#define MASTER_OFF_F (128 + 2 * STAGE_BYTES / 4)
#define CONV_SMEM    (512 + 2 * STAGE_BYTES + 65536)

// ---------------- scratch ----------------
__device__ float               g_h[N_BATCH * CIN * HWPIX];
__device__ __half              g_xs[(size_t)N_BATCH * 2 * PADPX * CIN];   // fp16 hi / lo*4096
__device__ __half              g_wsf[(size_t)2 * 9 * CIN * CIN];
__device__ float               g_fg[N_BATCH * NA];
__device__ float4              g_boxes[N_BATCH * NA];
__device__ unsigned            g_keys[N_BATCH * NA];
__device__ unsigned            g_cut[N_BATCH];
__device__ int                 g_cnt[N_BATCH];
__device__ unsigned long long  g_sel[N_BATCH][SORTN];
__device__ float4              g_bsort[N_BATCH][NPAD];
__device__ unsigned long long  g_masks[N_BATCH][NPAD][NCHUNK];

// ---------------- helpers ----------------
__device__ __forceinline__ uint32_t smem_u32(const void* p) {
    uint32_t a;
    asm("{ .reg .u64 t; cvta.to.shared.u64 t, %1; cvt.u32.u64 %0, t; }" : "=r"(a) : "l"(p));
    return a;
}
__device__ __forceinline__ unsigned f2key(float f) {
    unsigned u = __float_as_uint(f);
    return (u & 0x80000000u) ? ~u : (u | 0x80000000u);
}
__device__ __forceinline__ void anchor_base(int a, float* out) {
    const double ratios[3] = {0.5, 1.0, 2.0};
    const double scales[3] = {8.0, 16.0, 32.0};
    int ri = a / 3, si = a % 3;
    double h = 16.0 * scales[si] * sqrt(ratios[ri]);
    double w = 16.0 * scales[si] * sqrt(1.0 / ratios[ri]);
    out[0] = (float)(8.0 - h * 0.5);
    out[1] = (float)(8.0 - w * 0.5);
    out[2] = (float)(8.0 + h * 0.5);
    out[3] = (float)(8.0 + w * 0.5);
}

// ---------------- init ----------------
__global__ void init_k() {
    int idx = blockIdx.x * 256 + threadIdx.x;
    if (idx < N_BATCH) g_cnt[idx] = 0;
    if (idx < N_BATCH * SORTN) (&g_sel[0][0])[idx] = 0ull;
}

__global__ void xzero_k() {
    size_t idx = (size_t)blockIdx.x * 256 + threadIdx.x;
    size_t total = (size_t)N_BATCH * 2 * PADPX * CIN / 4;  // u64 chunks of halves
    if (idx < total) ((unsigned long long*)g_xs)[idx] = 0ull;
}

// split W1 -> g_wsf[s][tap][oc][ic]  (fp16 hi, lo*4096)
__global__ void wsplit_k(const float* __restrict__ W1) {
    int e = blockIdx.x * 256 + threadIdx.x;
    if (e >= 9 * CIN * CIN) return;
    int t = e / (CIN * CIN);
    int oi = e - t * (CIN * CIN);
    int oc = oi >> 9, ic = oi & 511;
    float w = W1[((size_t)oc * CIN + ic) * 9 + t];
    __half hi = __float2half(w);
    float lo = (w - __half2float(hi)) * 4096.f;
    size_t o = ((size_t)t * CIN + oc) * CIN + ic;
    g_wsf[o] = hi;
    g_wsf[o + (size_t)9 * CIN * CIN] = __float2half(lo);
}

// transpose + split x -> g_xs[n][s][prow*66+pcol][ic], interior at +1 offset
__global__ __launch_bounds__(256) void xsplit_k(const float* __restrict__ x) {
    __shared__ float s[64][65];
    int row = blockIdx.x, ic0 = blockIdx.y * 64, n = blockIdx.z;
    int tid = threadIdx.x;
    #pragma unroll
    for (int k = 0; k < 16; k++) {
        int idx = tid + k * 256;
        int ic_l = idx >> 6, p = idx & 63;
        s[ic_l][p] = x[((size_t)(n * CIN + ic0 + ic_l) << 12) + row * 64 + p];
    }
    __syncthreads();
    #pragma unroll
    for (int k = 0; k < 16; k++) {
        int idx = tid + k * 256;
        int p = idx >> 6, ic_l = idx & 63;
        float v = s[ic_l][p];
        __half hi = __float2half(v);
        float lo = (v - __half2float(hi)) * 4096.f;
        int prow = (row + 1) * 66 + (p + 1);
        size_t b = ((size_t)(n * 2) * PADPX + prow) * CIN + ic0 + ic_l;
        g_xs[b] = hi;
        g_xs[b + (size_t)PADPX * CIN] = __float2half(lo);
    }
}

// ---------------- conv3x3 via mma.sync fp16 3-term (scaled limbs), chunked accumulation ----------------
// grid (32 px-tiles, 4 oc-blocks, 4 n) = 512 CTAs, 256 threads (8 warps: 4m x 2n).
// Block tile 128px x 128oc; K=64 ic per iter; 216 iters: 72 hh + 72 hi*lo + 72 lo*hi.
// Work acc flushed to smem master every 4 iters (in-MMA K-chain <= 256); corr flushes scaled 2^-12.
__device__ __forceinline__ void conv_issue(int iter, uint32_t dstbase,
                                           int tid, int blkpx, int blkoc, int n) {
    int ph = iter / 72;
    int rem = iter - ph * 72;
    int tap = rem >> 3;
    int icc = (rem & 7) * 64;
    int ky = tap / 3, kx = tap - ky * 3;
    int sAs = (ph == 2) ? 1 : 0;
    int sWs = (ph == 1) ? 1 : 0;
    const __half* xbase = g_xs + (((size_t)(n * 2 + sAs)) * PADPX << 9) + icc;
    #pragma unroll
    for (int r = 0; r < 4; r++) {
        int idx = tid + r * 256;
        int arow = idx >> 3, q = idx & 7;
        int p = blkpx * 128 + arow;
        int ppix = ((p >> 6) + ky) * 66 + (p & 63) + kx;
        const __half* src = xbase + ((size_t)ppix << 9) + q * 8;
        uint32_t dst = dstbase + (uint32_t)(arow * 144 + q * 16);
        asm volatile("cp.async.cg.shared.global [%0], [%1], 16;" :: "r"(dst), "l"(src));
    }
    const __half* wbase = g_wsf + ((size_t)(sWs * 9 + tap) * 512 + blkoc * 128) * 512 + icc;
    #pragma unroll
    for (int r = 0; r < 4; r++) {
        int idx = tid + r * 256;
        int brow = idx >> 3, q = idx & 7;
        const __half* src = wbase + ((size_t)brow << 9) + q * 8;
        uint32_t dst = dstbase + (uint32_t)(18432 + brow * 144 + q * 16);
        asm volatile("cp.async.cg.shared.global [%0], [%1], 16;" :: "r"(dst), "l"(src));
    }
}

__global__ __launch_bounds__(256, 1) void conv_mma_k(const float* __restrict__ bias) {
    extern __shared__ float dyn[];
    float* sBias = dyn;                       // 128
    char* sStage = (char*)(dyn + 128);        // 2 stages of 36864B
    float* sMaster = dyn + MASTER_OFF_F;      // [e*256 + tid], 64 per thread
    uint32_t bufu = smem_u32(sStage);
    int tid = threadIdx.x, lane = tid & 31, warp = tid >> 5;
    int g = lane >> 2, tig = lane & 3;
    int warpm = warp & 3, warpn = warp >> 2;  // 4 x 2
    int blkpx = blockIdx.x, blkoc = blockIdx.y, n = blockIdx.z;
    if (tid < 128) sBias[tid] = bias[blkoc * 128 + tid];

    float work[2][8][4] = {};

    conv_issue(0, bufu, tid, blkpx, blkoc, n);
    asm volatile("cp.async.commit_group;" ::: "memory");

    for (int iter = 0; iter < 216; iter++) {
        asm volatile("cp.async.wait_group 0;" ::: "memory");
        __syncthreads();
        if (iter + 1 < 216) {
            conv_issue(iter + 1, bufu + (uint32_t)((iter + 1) & 1) * STAGE_BYTES,
                       tid, blkpx, blkoc, n);
            asm volatile("cp.async.commit_group;" ::: "memory");
        }
        const uint32_t* sA = (const uint32_t*)(sStage + (iter & 1) * STAGE_BYTES);
        const uint32_t* sB = sA + 4608;   // +18432 bytes

        #pragma unroll
        for (int ks = 0; ks < 4; ks++) {
            int kw = ks * 8;   // u32 offset of k-block
            uint32_t a[2][4];
            #pragma unroll
            for (int mt = 0; mt < 2; mt++) {
                int base = warpm * 32 + mt * 16;
                a[mt][0] = sA[(base + g) * 36 + kw + tig];
                a[mt][1] = sA[(base + g + 8) * 36 + kw + tig];
                a[mt][2] = sA[(base + g) * 36 + kw + 4 + tig];
                a[mt][3] = sA[(base + g + 8) * 36 + kw + 4 + tig];
            }
            #pragma unroll
            for (int nt = 0; nt < 8; nt++) {
                int col = warpn * 64 + nt * 8 + g;
                uint32_t b0 = sB[col * 36 + kw + tig];
                uint32_t b1 = sB[col * 36 + kw + 4 + tig];
                #pragma unroll
                for (int mt = 0; mt < 2; mt++) {
                    asm volatile(
                        "mma.sync.aligned.m16n8k16.row.col.f32.f16.f16.f32 "
                        "{%0,%1,%2,%3}, {%4,%5,%6,%7}, {%8,%9}, {%0,%1,%2,%3};"
                        : "+f"(work[mt][nt][0]), "+f"(work[mt][nt][1]),
                          "+f"(work[mt][nt][2]), "+f"(work[mt][nt][3])
                        : "r"(a[mt][0]), "r"(a[mt][1]), "r"(a[mt][2]), "r"(a[mt][3]),
                          "r"(b0), "r"(b1));
                }
            }
        }
        // flush every 4 iters (K-chain <= 256); corrections scaled 2^-12
        if ((iter & 3) == 3) {
            bool first = (iter == 3);
            bool corr = (iter >= 72);
            float sc = corr ? (1.f / 4096.f) : 1.f;
            #pragma unroll
            for (int mt = 0; mt < 2; mt++)
                #pragma unroll
                for (int nt = 0; nt < 8; nt++)
                    #pragma unroll
                    for (int q = 0; q < 4; q++) {
                        int e = ((mt * 8) + nt) * 4 + q;
                        float w = work[mt][nt][q] * sc;
                        if (first) sMaster[e * 256 + tid] = w;
                        else       sMaster[e * 256 + tid] += w;
                        work[mt][nt][q] = 0.f;
                    }
        }
    }
    __syncthreads();

    #pragma unroll
    for (int mt = 0; mt < 2; mt++) {
        int px = blkpx * 128 + warpm * 32 + mt * 16 + g;
        #pragma unroll
        for (int nt = 0; nt < 8; nt++) {
            int ocl = warpn * 64 + nt * 8 + 2 * tig;
            int oc = blkoc * 128 + ocl;
            float b0f = sBias[ocl], b1f = sBias[ocl + 1];
            size_t base0 = ((size_t)(n * CIN + oc) << 12);
            size_t base1 = ((size_t)(n * CIN + oc + 1) << 12);
            int e = ((mt * 8) + nt) * 4;
            g_h[base0 + px]     = fmaxf(sMaster[(e + 0) * 256 + tid] + b0f, 0.f);
            g_h[base1 + px]     = fmaxf(sMaster[(e + 1) * 256 + tid] + b1f, 0.f);
            g_h[base0 + px + 8] = fmaxf(sMaster[(e + 2) * 256 + tid] + b0f, 0.f);
            g_h[base1 + px + 8] = fmaxf(sMaster[(e + 3) * 256 + tid] + b1f, 0.f);
        }
    }
}

// ---------------- fused 1x1 heads + fg softmax ----------------
__global__ __launch_bounds__(256) void heads_k(const float* __restrict__ Wl,
                                               const float* __restrict__ bl,
                                               const float* __restrict__ Ws,
                                               const float* __restrict__ bs,
                                               float* __restrict__ dout) {
    int n = blockIdx.y;
    int p0 = blockIdx.x * 64;
    int tid = threadIdx.x;
    int pxg = tid & 15, cg = tid >> 4;
    int px0 = pxg * 4, c0 = cg * 4;

    __shared__ float sH[64][64];
    __shared__ float sWc[64][64];

    float acc[4][4] = {};

    for (int icc = 0; icc < CIN; icc += 64) {
        for (int idx = tid; idx < 4096; idx += 256) {
            int ic = idx >> 6, p = idx & 63;
            sH[ic][p] = g_h[(size_t)(n * CIN + icc + ic) * HWPIX + p0 + p];
        }
        for (int idx = tid; idx < 4096; idx += 256) {
            int ic = idx >> 6, c = idx & 63;
            float w = 0.f;
            if (c < 36)      w = Wl[(size_t)c * CIN + icc + ic];
            else if (c < 54) w = Ws[(size_t)(c - 36) * CIN + icc + ic];
            sWc[ic][c] = w;
        }
        __syncthreads();
        #pragma unroll 16
        for (int ic = 0; ic < 64; ic++) {
            float w0 = sWc[ic][c0 + 0], w1 = sWc[ic][c0 + 1];
            float w2 = sWc[ic][c0 + 2], w3 = sWc[ic][c0 + 3];
            float v0 = sH[ic][px0 + 0], v1 = sH[ic][px0 + 1];
            float v2 = sH[ic][px0 + 2], v3 = sH[ic][px0 + 3];
            acc[0][0] += w0 * v0; acc[0][1] += w0 * v1; acc[0][2] += w0 * v2; acc[0][3] += w0 * v3;
            acc[1][0] += w1 * v0; acc[1][1] += w1 * v1; acc[1][2] += w1 * v2; acc[1][3] += w1 * v3;
            acc[2][0] += w2 * v0; acc[2][1] += w2 * v1; acc[2][2] += w2 * v2; acc[2][3] += w2 * v3;
            acc[3][0] += w3 * v0; acc[3][1] += w3 * v1; acc[3][2] += w3 * v2; acc[3][3] += w3 * v3;
        }
        __syncthreads();
    }

    float val[4][4];
    #pragma unroll
    for (int ci = 0; ci < 4; ci++) {
        int cc = c0 + ci;
        float bv = (cc < 36) ? bl[cc] : ((cc < 54) ? bs[cc - 36] : 0.f);
        #pragma unroll
        for (int pi = 0; pi < 4; pi++) val[ci][pi] = acc[ci][pi] + bv;
    }
    #pragma unroll
    for (int ci = 0; ci < 4; ci++) {
        int cc = c0 + ci;
        #pragma unroll
        for (int pi = 0; pi < 4; pi++) {
            int p = p0 + px0 + pi;
            if (cc < 36)
                dout[LOCS_OFF + (size_t)n * 147456 + (size_t)p * 36 + cc] = val[ci][pi];
            else if (cc < 54)
                dout[SCORES_OFF + (size_t)n * 73728 + (size_t)p * 18 + (cc - 36)] = val[ci][pi];
        }
    }
    if (c0 >= 36 && c0 < 54) {
        #pragma unroll
        for (int pr = 0; pr < 2; pr++) {
            int ce = c0 + 2 * pr;
            if (ce + 1 < 54) {
                int a = (ce - 36) >> 1;
                #pragma unroll
                for (int pi = 0; pi < 4; pi++) {
                    float d = val[2 * pr + 1][pi] - val[2 * pr][pi];
                    float fg = 1.f / (1.f + expf(-d));
                    g_fg[n * NA + (p0 + px0 + pi) * 9 + a] = fg;
                }
            }
        }
    }
}

// ---------------- anchors ----------------
__global__ void anchors_k(float* __restrict__ dout) {
    int j = blockIdx.x * 256 + threadIdx.x;
    if (j >= NA) return;
    int p = j / 9, a = j % 9;
    int y = p >> 6, xx = p & 63;
    float ab[4];
    anchor_base(a, ab);
    float* o = dout + ANCH_OFF + (size_t)j * 4;
    o[0] = y * 16.f + ab[0];
    o[1] = xx * 16.f + ab[1];
    o[2] = y * 16.f + ab[2];
    o[3] = xx * 16.f + ab[3];
}

// ---------------- loc2bbox + clip + min-size + key ----------------
__global__ void boxes_k(const float* __restrict__ dout,
                        const int* __restrict__ pih, const int* __restrict__ piw) {
    int idx = blockIdx.x * 256 + threadIdx.x;
    if (idx >= N_BATCH * NA) return;
    int n = idx / NA, j = idx - n * NA;
    int p = j / 9, a = j - p * 9;
    int y = p >> 6, xx = p & 63;
    float ab[4];
    anchor_base(a, ab);
    float a0 = y * 16.f + ab[0], a1 = xx * 16.f + ab[1];
    float a2 = y * 16.f + ab[2], a3 = xx * 16.f + ab[3];

    const float* loc = dout + LOCS_OFF + (size_t)n * 147456 + (size_t)j * 4;
    float dy = loc[0], dx = loc[1], dh = loc[2], dw = loc[3];

    float src_h = a2 - a0, src_w = a3 - a1;
    float ctr_y = a0 + 0.5f * src_h, ctr_x = a1 + 0.5f * src_w;
    float cy = dy * src_h + ctr_y;
    float cx = dx * src_w + ctr_x;
    float hh = expf(dh) * src_h;
    float ww = expf(dw) * src_w;

    float fh = (float)(*pih), fw = (float)(*piw);
    float y1 = fminf(fmaxf(cy - 0.5f * hh, 0.f), fh);
    float y2 = fminf(fmaxf(cy + 0.5f * hh, 0.f), fh);
    float x1 = fminf(fmaxf(cx - 0.5f * ww, 0.f), fw);
    float x2 = fminf(fmaxf(cx + 0.5f * ww, 0.f), fw);

    bool valid = ((y2 - y1) >= 16.f) && ((x2 - x1) >= 16.f);
    float sc = valid ? g_fg[idx] : -INFINITY;

    g_boxes[idx] = make_float4(y1, x1, y2, x2);
    g_keys[idx] = f2key(sc);
}

// ---------------- radix select ----------------
__global__ __launch_bounds__(1024) void select_k() {
    int n = blockIdx.x;
    const unsigned* keys = g_keys + (size_t)n * NA;
    __shared__ unsigned hist[256];
    __shared__ unsigned sprefix;
    __shared__ int srem;
    if (threadIdx.x == 0) { sprefix = 0u; srem = NPRE; }
    __syncthreads();
    for (int pass = 0; pass < 4; pass++) {
        for (int b = threadIdx.x; b < 256; b += 1024) hist[b] = 0u;
        __syncthreads();
        int shift = 24 - 8 * pass;
        unsigned maskhi = pass ? (0xFFFFFFFFu << (32 - 8 * pass)) : 0u;
        unsigned pref = sprefix;
        for (int i = threadIdx.x; i < NA; i += 1024) {
            unsigned k = keys[i];
            if ((k & maskhi) == pref) atomicAdd(&hist[(k >> shift) & 0xFF], 1u);
        }
        __syncthreads();
        if (threadIdx.x == 0) {
            unsigned cum = 0;
            int rem = srem;
            for (int b = 255; b >= 0; b--) {
                cum += hist[b];
                if ((int)cum >= rem) {
                    srem = rem - (int)(cum - hist[b]);
                    sprefix = pref | ((unsigned)b << shift);
                    break;
                }
            }
        }
        __syncthreads();
    }
    if (threadIdx.x == 0) g_cut[n] = sprefix;
}

// ---------------- compact ----------------
__global__ void compact_k() {
    int idx = blockIdx.x * 256 + threadIdx.x;
    if (idx >= N_BATCH * NA) return;
    int n = idx / NA;
    unsigned k = g_keys[idx];
    if (k >= g_cut[n]) {
        int pos = atomicAdd(&g_cnt[n], 1);
        if (pos < SORTN) {
            unsigned j = (unsigned)(idx - n * NA);
            g_sel[n][pos] = ((unsigned long long)k << 32) | (0xFFFFFFFFu - j);
        }
    }
}

// ---------------- bitonic sort + gather ----------------
__global__ __launch_bounds__(1024) void sort_k() {
    int n = blockIdx.x;
    extern __shared__ unsigned long long sh[];
    for (int i = threadIdx.x; i < SORTN; i += 1024) sh[i] = g_sel[n][i];
    __syncthreads();
    for (int k = 2; k <= SORTN; k <<= 1) {
        for (int j = k >> 1; j > 0; j >>= 1) {
            for (int i = threadIdx.x; i < SORTN; i += 1024) {
                int ixj = i ^ j;
                if (ixj > i) {
                    unsigned long long a = sh[i], b = sh[ixj];
                    bool up = (i & k) == 0;
                    if (up ? (a < b) : (a > b)) { sh[i] = b; sh[ixj] = a; }
                }
            }
            __syncthreads();
        }
    }
    for (int r = threadIdx.x; r < NPRE; r += 1024) {
        unsigned long long comp = sh[r];
        unsigned j = 0xFFFFFFFFu - (unsigned)(comp & 0xFFFFFFFFull);
        if (j >= NA) j = NA - 1;
        g_bsort[n][r] = g_boxes[(size_t)n * NA + j];
    }
}

// ---------------- NMS masks ----------------
__global__ __launch_bounds__(64) void masks_k() {
    int n = blockIdx.z, ci = blockIdx.y, cj = blockIdx.x;
    int t = threadIdx.x;
    int i = ci * 64 + t;
    if (cj < ci) { g_masks[n][i][cj] = 0ull; return; }
    __shared__ float4 bj[64];
    int jg = cj * 64 + t;
    bj[t] = (jg < NPRE) ? g_bsort[n][jg] : make_float4(0.f, 0.f, 0.f, 0.f);
    __syncthreads();
    if (i >= NPRE) { g_masks[n][i][cj] = 0ull; return; }
    float4 bi = g_bsort[n][i];
    float areai = (bi.z - bi.x) * (bi.w - bi.y);
    unsigned long long m = 0ull;
    int jbase = cj * 64;
    #pragma unroll 8
    for (int jj = 0; jj < 64; jj++) {
        int jgl = jbase + jj;
        if (jgl > i && jgl < NPRE) {
            float4 bb = bj[jj];
            float ty1 = fmaxf(bi.x, bb.x), tx1 = fmaxf(bi.y, bb.y);
            float ty2 = fminf(bi.z, bb.z), tx2 = fminf(bi.w, bb.w);
            float ihh = fmaxf(ty2 - ty1, 0.f), iww = fmaxf(tx2 - tx1, 0.f);
            float inter = ihh * iww;
            float areaj = (bb.z - bb.x) * (bb.w - bb.y);
            float iou = inter / (areai + areaj - inter + 1e-10f);
            if (iou > 0.7f) m |= (1ull << jj);
        }
    }
    g_masks[n][i][cj] = m;
}

// ---------------- single-warp NMS reduction (depth-8 prefetch, R8 version) + emit ----------------
__global__ __launch_bounds__(32) void nms_emit_k(float* __restrict__ dout) {
    int n = blockIdx.x;
    int l = threadIdx.x;
    int c0 = l, c1 = l + 32, c2 = l + 64;
    bool v2 = c2 < NCHUNK;
    unsigned long long rv0 = 0, rv1 = 0, rv2 = 0;
    unsigned long long b0[8], b1[8], b2[8];
    #pragma unroll
    for (int s = 0; s < 8; s++) {
        b0[s] = g_masks[n][s][c0];
        b1[s] = g_masks[n][s][c1];
        b2[s] = v2 ? g_masks[n][s][c2] : 0ull;
    }
    for (int ib = 0; ib < NPRE; ib += 8) {
        #pragma unroll
        for (int s = 0; s < 8; s++) {
            int i = ib + s;
            unsigned long long cm0 = b0[s], cm1 = b1[s], cm2 = b2[s];
            if (i + 8 < NPRE) {
                b0[s] = g_masks[n][i + 8][c0];
                b1[s] = g_masks[n][i + 8][c1];
                b2[s] = v2 ? g_masks[n][i + 8][c2] : 0ull;
            }
            int ch = i >> 6, slot = ch >> 5, src = ch & 31;
            unsigned long long rsel = (slot == 0) ? rv0 : ((slot == 1) ? rv1 : rv2);
            unsigned long long v = __shfl_sync(0xFFFFFFFFu, rsel, src);
            if (!((v >> (i & 63)) & 1ull)) { rv0 |= cm0; rv1 |= cm1; rv2 |= cm2; }
        }
    }
    __shared__ unsigned long long remv[96];
    remv[l] = rv0; remv[l + 32] = rv1;
    if (v2) remv[l + 64] = rv2;
    __syncwarp();
    float* rind = dout + RIND_OFF + n * NPOST;
    for (int q = l; q < NPOST; q += 32) rind[q] = (float)n;
    if (l == 0) {
        float4* rois = (float4*)(dout + ROIS_OFF) + n * NPOST;
        int r = 0;
        for (int i = 0; i < NPRE && r < NPOST; i++)
            if (((remv[i >> 6] >> (i & 63)) & 1ull) == 0ull) rois[r++] = g_bsort[n][i];
        for (int i = 0; i < NPRE && r < NPOST; i++)
            if (((remv[i >> 6] >> (i & 63)) & 1ull) != 0ull) rois[r++] = g_bsort[n][i];
    }
}

// ---------------- launch ----------------
extern "C" void kernel_launch(void* const* d_in, const int* in_sizes, int n_in,
                              void* d_out, int out_size) {
    const float* x  = (const float*)d_in[0];
    const float* W1 = (const float*)d_in[1];
    const float* b1 = (const float*)d_in[2];
    const float* Ws = (const float*)d_in[3];
    const float* bs = (const float*)d_in[4];
    const float* Wl = (const float*)d_in[5];
    const float* bl = (const float*)d_in[6];
    const int* ih   = (const int*)d_in[7];
    const int* iw   = (const int*)d_in[8];
    float* out = (float*)d_out;

    cudaFuncSetAttribute(sort_k, cudaFuncAttributeMaxDynamicSharedMemorySize, SORTN * 8);
    cudaFuncSetAttribute(conv_mma_k, cudaFuncAttributeMaxDynamicSharedMemorySize, CONV_SMEM);

    init_k<<<(N_BATCH * SORTN + 255) / 256, 256>>>();
    xzero_k<<<(int)(((size_t)N_BATCH * 2 * PADPX * CIN / 4 + 255) / 256), 256>>>();
    wsplit_k<<<(9 * CIN * CIN + 255) / 256, 256>>>(W1);
    xsplit_k<<<dim3(64, 8, 4), 256>>>(x);
    conv_mma_k<<<dim3(32, 4, 4), 256, CONV_SMEM>>>(b1);
    heads_k<<<dim3(64, 4), 256>>>(Wl, bl, Ws, bs, out);
    anchors_k<<<(NA + 255) / 256, 256>>>(out);
    boxes_k<<<(N_BATCH * NA + 255) / 256, 256>>>(out, ih, iw);
    select_k<<<N_BATCH, 1024>>>();
    compact_k<<<(N_BATCH * NA + 255) / 256, 256>>>();
    sort_k<<<N_BATCH, 1024, SORTN * 8>>>();
    masks_k<<<dim3(NCHUNK, NCHUNK, N_BATCH), 64>>>();
    nms_emit_k<<<N_BATCH, 32>>>(out);
}

// round 13
// speedup vs baseline: 1.5346x; 1.0254x over previous
#include <cuda_runtime.h>
#include <cuda_fp16.h>
#include <math.h>
#include <stdint.h>

#define N_BATCH 4
#define CIN     512
#define HWPIX   4096
#define NA      36864
#define NPRE    6000
#define NPOST   300
#define NCHUNK  94
#define NPAD    6016
#define SORTN   8192
#define PADPX   4356      // 66*66

#define LOCS_OFF   0
#define SCORES_OFF 589824
#define ROIS_OFF   884736
#define RIND_OFF   889536
#define ANCH_OFF   890736

// conv smem: 128 bias floats + 2 stages of (A 64x144B + B 128x144B) + master 32x256 floats
// = 512 + 2*27648 + 32768 = 88576 B  -> 2 CTAs/SM (2*88576 < 227KB)
#define STAGE_BYTES  27648
#define MASTER_OFF_F (128 + 2 * STAGE_BYTES / 4)     // float index 13952
#define CONV_SMEM    88576

// ---------------- scratch ----------------
__device__ float               g_h[N_BATCH * CIN * HWPIX];
__device__ __half              g_xs[(size_t)N_BATCH * 2 * PADPX * CIN];   // fp16 hi / lo*4096
__device__ __half              g_wsf[(size_t)2 * 9 * CIN * CIN];
__device__ float               g_fg[N_BATCH * NA];
__device__ float4              g_boxes[N_BATCH * NA];
__device__ unsigned            g_keys[N_BATCH * NA];
__device__ unsigned            g_cut[N_BATCH];
__device__ int                 g_cnt[N_BATCH];
__device__ unsigned long long  g_sel[N_BATCH][SORTN];
__device__ float4              g_bsort[N_BATCH][NPAD];
__device__ unsigned long long  g_masks[N_BATCH][NPAD][NCHUNK];

// ---------------- helpers ----------------
__device__ __forceinline__ uint32_t smem_u32(const void* p) {
    uint32_t a;
    asm("{ .reg .u64 t; cvta.to.shared.u64 t, %1; cvt.u32.u64 %0, t; }" : "=r"(a) : "l"(p));
    return a;
}
__device__ __forceinline__ unsigned f2key(float f) {
    unsigned u = __float_as_uint(f);
    return (u & 0x80000000u) ? ~u : (u | 0x80000000u);
}
__device__ __forceinline__ void anchor_base(int a, float* out) {
    const double ratios[3] = {0.5, 1.0, 2.0};
    const double scales[3] = {8.0, 16.0, 32.0};
    int ri = a / 3, si = a % 3;
    double h = 16.0 * scales[si] * sqrt(ratios[ri]);
    double w = 16.0 * scales[si] * sqrt(1.0 / ratios[ri]);
    out[0] = (float)(8.0 - h * 0.5);
    out[1] = (float)(8.0 - w * 0.5);
    out[2] = (float)(8.0 + h * 0.5);
    out[3] = (float)(8.0 + w * 0.5);
}

// ---------------- init ----------------
__global__ void init_k() {
    int idx = blockIdx.x * 256 + threadIdx.x;
    if (idx < N_BATCH) g_cnt[idx] = 0;
    if (idx < N_BATCH * SORTN) (&g_sel[0][0])[idx] = 0ull;
}

__global__ void xzero_k() {
    size_t idx = (size_t)blockIdx.x * 256 + threadIdx.x;
    size_t total = (size_t)N_BATCH * 2 * PADPX * CIN / 4;  // u64 chunks of halves
    if (idx < total) ((unsigned long long*)g_xs)[idx] = 0ull;
}

// split W1 -> g_wsf[s][tap][oc][ic]  (fp16 hi, lo*4096)
__global__ void wsplit_k(const float* __restrict__ W1) {
    int e = blockIdx.x * 256 + threadIdx.x;
    if (e >= 9 * CIN * CIN) return;
    int t = e / (CIN * CIN);
    int oi = e - t * (CIN * CIN);
    int oc = oi >> 9, ic = oi & 511;
    float w = W1[((size_t)oc * CIN + ic) * 9 + t];
    __half hi = __float2half(w);
    float lo = (w - __half2float(hi)) * 4096.f;
    size_t o = ((size_t)t * CIN + oc) * CIN + ic;
    g_wsf[o] = hi;
    g_wsf[o + (size_t)9 * CIN * CIN] = __float2half(lo);
}

// transpose + split x -> g_xs[n][s][prow*66+pcol][ic], interior at +1 offset
__global__ __launch_bounds__(256) void xsplit_k(const float* __restrict__ x) {
    __shared__ float s[64][65];
    int row = blockIdx.x, ic0 = blockIdx.y * 64, n = blockIdx.z;
    int tid = threadIdx.x;
    #pragma unroll
    for (int k = 0; k < 16; k++) {
        int idx = tid + k * 256;
        int ic_l = idx >> 6, p = idx & 63;
        s[ic_l][p] = x[((size_t)(n * CIN + ic0 + ic_l) << 12) + row * 64 + p];
    }
    __syncthreads();
    #pragma unroll
    for (int k = 0; k < 16; k++) {
        int idx = tid + k * 256;
        int p = idx >> 6, ic_l = idx & 63;
        float v = s[ic_l][p];
        __half hi = __float2half(v);
        float lo = (v - __half2float(hi)) * 4096.f;
        int prow = (row + 1) * 66 + (p + 1);
        size_t b = ((size_t)(n * 2) * PADPX + prow) * CIN + ic0 + ic_l;
        g_xs[b] = hi;
        g_xs[b + (size_t)PADPX * CIN] = __float2half(lo);
    }
}

// ---------------- conv3x3 via mma.sync fp16 3-term (scaled limbs), chunked accumulation ----------------
// grid (64 px-tiles, 4 oc-blocks, 4 n) = 1024 CTAs, 256 threads (8 warps: 2m x 4n), 2 CTAs/SM.
// Block tile 64px x 128oc; K=64 ic per iter; 216 iters: 72 hh + 72 hi*lo + 72 lo*hi.
// Work acc flushed to smem master every 4 iters (in-MMA K-chain <= 256); corr flushes scaled 2^-12.
// Bit-exact vs the 128px-tile version: identical per-output MMA/flush sequence.
__device__ __forceinline__ void conv_issue(int iter, uint32_t dstbase,
                                           int tid, int blkpx, int blkoc, int n) {
    int ph = iter / 72;
    int rem = iter - ph * 72;
    int tap = rem >> 3;
    int icc = (rem & 7) * 64;
    int ky = tap / 3, kx = tap - ky * 3;
    int sAs = (ph == 2) ? 1 : 0;
    int sWs = (ph == 1) ? 1 : 0;
    const __half* xbase = g_xs + (((size_t)(n * 2 + sAs)) * PADPX << 9) + icc;
    // A tile: 64 rows (pixels of row blkpx) x 128B, 512 chunks = 2 rounds
    #pragma unroll
    for (int r = 0; r < 2; r++) {
        int idx = tid + r * 256;
        int arow = idx >> 3, q = idx & 7;
        int ppix = (blkpx + ky) * 66 + arow + kx;
        const __half* src = xbase + ((size_t)ppix << 9) + q * 8;
        uint32_t dst = dstbase + (uint32_t)(arow * 144 + q * 16);
        asm volatile("cp.async.cg.shared.global [%0], [%1], 16;" :: "r"(dst), "l"(src));
    }
    // B tile: 128 oc rows x 128B, 1024 chunks = 4 rounds
    const __half* wbase = g_wsf + ((size_t)(sWs * 9 + tap) * 512 + blkoc * 128) * 512 + icc;
    #pragma unroll
    for (int r = 0; r < 4; r++) {
        int idx = tid + r * 256;
        int brow = idx >> 3, q = idx & 7;
        const __half* src = wbase + ((size_t)brow << 9) + q * 8;
        uint32_t dst = dstbase + (uint32_t)(9216 + brow * 144 + q * 16);
        asm volatile("cp.async.cg.shared.global [%0], [%1], 16;" :: "r"(dst), "l"(src));
    }
}

__global__ __launch_bounds__(256, 2) void conv_mma_k(const float* __restrict__ bias) {
    extern __shared__ float dyn[];
    float* sBias = dyn;                       // 128
    char* sStage = (char*)(dyn + 128);        // 2 stages of 27648B
    float* sMaster = dyn + MASTER_OFF_F;      // [e*256 + tid], 32 per thread
    uint32_t bufu = smem_u32(sStage);
    int tid = threadIdx.x, lane = tid & 31, warp = tid >> 5;
    int g = lane >> 2, tig = lane & 3;
    int warpm = warp & 1, warpn = warp >> 1;  // 2 x 4
    int blkpx = blockIdx.x, blkoc = blockIdx.y, n = blockIdx.z;
    if (tid < 128) sBias[tid] = bias[blkoc * 128 + tid];

    float work[2][4][4] = {};

    conv_issue(0, bufu, tid, blkpx, blkoc, n);
    asm volatile("cp.async.commit_group;" ::: "memory");

    for (int iter = 0; iter < 216; iter++) {
        asm volatile("cp.async.wait_group 0;" ::: "memory");
        __syncthreads();
        if (iter + 1 < 216) {
            conv_issue(iter + 1, bufu + (uint32_t)((iter + 1) & 1) * STAGE_BYTES,
                       tid, blkpx, blkoc, n);
            asm volatile("cp.async.commit_group;" ::: "memory");
        }
        const uint32_t* sA = (const uint32_t*)(sStage + (iter & 1) * STAGE_BYTES);
        const uint32_t* sB = sA + 2304;   // +9216 bytes

        #pragma unroll
        for (int ks = 0; ks < 4; ks++) {
            int kw = ks * 8;   // u32 offset of k-block
            uint32_t a[2][4];
            #pragma unroll
            for (int mt = 0; mt < 2; mt++) {
                int base = warpm * 32 + mt * 16;
                a[mt][0] = sA[(base + g) * 36 + kw + tig];
                a[mt][1] = sA[(base + g + 8) * 36 + kw + tig];
                a[mt][2] = sA[(base + g) * 36 + kw + 4 + tig];
                a[mt][3] = sA[(base + g + 8) * 36 + kw + 4 + tig];
            }
            #pragma unroll
            for (int nt = 0; nt < 4; nt++) {
                int col = warpn * 32 + nt * 8 + g;
                uint32_t b0 = sB[col * 36 + kw + tig];
                uint32_t b1 = sB[col * 36 + kw + 4 + tig];
                #pragma unroll
                for (int mt = 0; mt < 2; mt++) {
                    asm volatile(
                        "mma.sync.aligned.m16n8k16.row.col.f32.f16.f16.f32 "
                        "{%0,%1,%2,%3}, {%4,%5,%6,%7}, {%8,%9}, {%0,%1,%2,%3};"
                        : "+f"(work[mt][nt][0]), "+f"(work[mt][nt][1]),
                          "+f"(work[mt][nt][2]), "+f"(work[mt][nt][3])
                        : "r"(a[mt][0]), "r"(a[mt][1]), "r"(a[mt][2]), "r"(a[mt][3]),
                          "r"(b0), "r"(b1));
                }
            }
        }
        // flush every 4 iters (K-chain <= 256); corrections scaled 2^-12
        if ((iter & 3) == 3) {
            bool first = (iter == 3);
            bool corr = (iter >= 72);
            float sc = corr ? (1.f / 4096.f) : 1.f;
            #pragma unroll
            for (int mt = 0; mt < 2; mt++)
                #pragma unroll
                for (int nt = 0; nt < 4; nt++)
                    #pragma unroll
                    for (int q = 0; q < 4; q++) {
                        int e = ((mt * 4) + nt) * 4 + q;
                        float w = work[mt][nt][q] * sc;
                        if (first) sMaster[e * 256 + tid] = w;
                        else       sMaster[e * 256 + tid] += w;
                        work[mt][nt][q] = 0.f;
                    }
        }
    }
    __syncthreads();

    #pragma unroll
    for (int mt = 0; mt < 2; mt++) {
        int px = blkpx * 64 + warpm * 32 + mt * 16 + g;
        #pragma unroll
        for (int nt = 0; nt < 4; nt++) {
            int ocl = warpn * 32 + nt * 8 + 2 * tig;
            int oc = blkoc * 128 + ocl;
            float b0f = sBias[ocl], b1f = sBias[ocl + 1];
            size_t base0 = ((size_t)(n * CIN + oc) << 12);
            size_t base1 = ((size_t)(n * CIN + oc + 1) << 12);
            int e = ((mt * 4) + nt) * 4;
            g_h[base0 + px]     = fmaxf(sMaster[(e + 0) * 256 + tid] + b0f, 0.f);
            g_h[base1 + px]     = fmaxf(sMaster[(e + 1) * 256 + tid] + b1f, 0.f);
            g_h[base0 + px + 8] = fmaxf(sMaster[(e + 2) * 256 + tid] + b0f, 0.f);
            g_h[base1 + px + 8] = fmaxf(sMaster[(e + 3) * 256 + tid] + b1f, 0.f);
        }
    }
}

// ---------------- fused 1x1 heads + fg softmax ----------------
__global__ __launch_bounds__(256) void heads_k(const float* __restrict__ Wl,
                                               const float* __restrict__ bl,
                                               const float* __restrict__ Ws,
                                               const float* __restrict__ bs,
                                               float* __restrict__ dout) {
    int n = blockIdx.y;
    int p0 = blockIdx.x * 64;
    int tid = threadIdx.x;
    int pxg = tid & 15, cg = tid >> 4;
    int px0 = pxg * 4, c0 = cg * 4;

    __shared__ float sH[64][64];
    __shared__ float sWc[64][64];

    float acc[4][4] = {};

    for (int icc = 0; icc < CIN; icc += 64) {
        for (int idx = tid; idx < 4096; idx += 256) {
            int ic = idx >> 6, p = idx & 63;
            sH[ic][p] = g_h[(size_t)(n * CIN + icc + ic) * HWPIX + p0 + p];
        }
        for (int idx = tid; idx < 4096; idx += 256) {
            int ic = idx >> 6, c = idx & 63;
            float w = 0.f;
            if (c < 36)      w = Wl[(size_t)c * CIN + icc + ic];
            else if (c < 54) w = Ws[(size_t)(c - 36) * CIN + icc + ic];
            sWc[ic][c] = w;
        }
        __syncthreads();
        #pragma unroll 16
        for (int ic = 0; ic < 64; ic++) {
            float w0 = sWc[ic][c0 + 0], w1 = sWc[ic][c0 + 1];
            float w2 = sWc[ic][c0 + 2], w3 = sWc[ic][c0 + 3];
            float v0 = sH[ic][px0 + 0], v1 = sH[ic][px0 + 1];
            float v2 = sH[ic][px0 + 2], v3 = sH[ic][px0 + 3];
            acc[0][0] += w0 * v0; acc[0][1] += w0 * v1; acc[0][2] += w0 * v2; acc[0][3] += w0 * v3;
            acc[1][0] += w1 * v0; acc[1][1] += w1 * v1; acc[1][2] += w1 * v2; acc[1][3] += w1 * v3;
            acc[2][0] += w2 * v0; acc[2][1] += w2 * v1; acc[2][2] += w2 * v2; acc[2][3] += w2 * v3;
            acc[3][0] += w3 * v0; acc[3][1] += w3 * v1; acc[3][2] += w3 * v2; acc[3][3] += w3 * v3;
        }
        __syncthreads();
    }

    float val[4][4];
    #pragma unroll
    for (int ci = 0; ci < 4; ci++) {
        int cc = c0 + ci;
        float bv = (cc < 36) ? bl[cc] : ((cc < 54) ? bs[cc - 36] : 0.f);
        #pragma unroll
        for (int pi = 0; pi < 4; pi++) val[ci][pi] = acc[ci][pi] + bv;
    }
    #pragma unroll
    for (int ci = 0; ci < 4; ci++) {
        int cc = c0 + ci;
        #pragma unroll
        for (int pi = 0; pi < 4; pi++) {
            int p = p0 + px0 + pi;
            if (cc < 36)
                dout[LOCS_OFF + (size_t)n * 147456 + (size_t)p * 36 + cc] = val[ci][pi];
            else if (cc < 54)
                dout[SCORES_OFF + (size_t)n * 73728 + (size_t)p * 18 + (cc - 36)] = val[ci][pi];
        }
    }
    if (c0 >= 36 && c0 < 54) {
        #pragma unroll
        for (int pr = 0; pr < 2; pr++) {
            int ce = c0 + 2 * pr;
            if (ce + 1 < 54) {
                int a = (ce - 36) >> 1;
                #pragma unroll
                for (int pi = 0; pi < 4; pi++) {
                    float d = val[2 * pr + 1][pi] - val[2 * pr][pi];
                    float fg = 1.f / (1.f + expf(-d));
                    g_fg[n * NA + (p0 + px0 + pi) * 9 + a] = fg;
                }
            }
        }
    }
}

// ---------------- anchors ----------------
__global__ void anchors_k(float* __restrict__ dout) {
    int j = blockIdx.x * 256 + threadIdx.x;
    if (j >= NA) return;
    int p = j / 9, a = j % 9;
    int y = p >> 6, xx = p & 63;
    float ab[4];
    anchor_base(a, ab);
    float* o = dout + ANCH_OFF + (size_t)j * 4;
    o[0] = y * 16.f + ab[0];
    o[1] = xx * 16.f + ab[1];
    o[2] = y * 16.f + ab[2];
    o[3] = xx * 16.f + ab[3];
}

// ---------------- loc2bbox + clip + min-size + key ----------------
__global__ void boxes_k(const float* __restrict__ dout,
                        const int* __restrict__ pih, const int* __restrict__ piw) {
    int idx = blockIdx.x * 256 + threadIdx.x;
    if (idx >= N_BATCH * NA) return;
    int n = idx / NA, j = idx - n * NA;
    int p = j / 9, a = j - p * 9;
    int y = p >> 6, xx = p & 63;
    float ab[4];
    anchor_base(a, ab);
    float a0 = y * 16.f + ab[0], a1 = xx * 16.f + ab[1];
    float a2 = y * 16.f + ab[2], a3 = xx * 16.f + ab[3];

    const float* loc = dout + LOCS_OFF + (size_t)n * 147456 + (size_t)j * 4;
    float dy = loc[0], dx = loc[1], dh = loc[2], dw = loc[3];

    float src_h = a2 - a0, src_w = a3 - a1;
    float ctr_y = a0 + 0.5f * src_h, ctr_x = a1 + 0.5f * src_w;
    float cy = dy * src_h + ctr_y;
    float cx = dx * src_w + ctr_x;
    float hh = expf(dh) * src_h;
    float ww = expf(dw) * src_w;

    float fh = (float)(*pih), fw = (float)(*piw);
    float y1 = fminf(fmaxf(cy - 0.5f * hh, 0.f), fh);
    float y2 = fminf(fmaxf(cy + 0.5f * hh, 0.f), fh);
    float x1 = fminf(fmaxf(cx - 0.5f * ww, 0.f), fw);
    float x2 = fminf(fmaxf(cx + 0.5f * ww, 0.f), fw);

    bool valid = ((y2 - y1) >= 16.f) && ((x2 - x1) >= 16.f);
    float sc = valid ? g_fg[idx] : -INFINITY;

    g_boxes[idx] = make_float4(y1, x1, y2, x2);
    g_keys[idx] = f2key(sc);
}

// ---------------- radix select ----------------
__global__ __launch_bounds__(1024) void select_k() {
    int n = blockIdx.x;
    const unsigned* keys = g_keys + (size_t)n * NA;
    __shared__ unsigned hist[256];
    __shared__ unsigned sprefix;
    __shared__ int srem;
    if (threadIdx.x == 0) { sprefix = 0u; srem = NPRE; }
    __syncthreads();
    for (int pass = 0; pass < 4; pass++) {
        for (int b = threadIdx.x; b < 256; b += 1024) hist[b] = 0u;
        __syncthreads();
        int shift = 24 - 8 * pass;
        unsigned maskhi = pass ? (0xFFFFFFFFu << (32 - 8 * pass)) : 0u;
        unsigned pref = sprefix;
        for (int i = threadIdx.x; i < NA; i += 1024) {
            unsigned k = keys[i];
            if ((k & maskhi) == pref) atomicAdd(&hist[(k >> shift) & 0xFF], 1u);
        }
        __syncthreads();
        if (threadIdx.x == 0) {
            unsigned cum = 0;
            int rem = srem;
            for (int b = 255; b >= 0; b--) {
                cum += hist[b];
                if ((int)cum >= rem) {
                    srem = rem - (int)(cum - hist[b]);
                    sprefix = pref | ((unsigned)b << shift);
                    break;
                }
            }
        }
        __syncthreads();
    }
    if (threadIdx.x == 0) g_cut[n] = sprefix;
}

// ---------------- compact ----------------
__global__ void compact_k() {
    int idx = blockIdx.x * 256 + threadIdx.x;
    if (idx >= N_BATCH * NA) return;
    int n = idx / NA;
    unsigned k = g_keys[idx];
    if (k >= g_cut[n]) {
        int pos = atomicAdd(&g_cnt[n], 1);
        if (pos < SORTN) {
            unsigned j = (unsigned)(idx - n * NA);
            g_sel[n][pos] = ((unsigned long long)k << 32) | (0xFFFFFFFFu - j);
        }
    }
}

// ---------------- bitonic sort + gather ----------------
__global__ __launch_bounds__(1024) void sort_k() {
    int n = blockIdx.x;
    extern __shared__ unsigned long long sh[];
    for (int i = threadIdx.x; i < SORTN; i += 1024) sh[i] = g_sel[n][i];
    __syncthreads();
    for (int k = 2; k <= SORTN; k <<= 1) {
        for (int j = k >> 1; j > 0; j >>= 1) {
            for (int i = threadIdx.x; i < SORTN; i += 1024) {
                int ixj = i ^ j;
                if (ixj > i) {
                    unsigned long long a = sh[i], b = sh[ixj];
                    bool up = (i & k) == 0;
                    if (up ? (a < b) : (a > b)) { sh[i] = b; sh[ixj] = a; }
                }
            }
            __syncthreads();
        }
    }
    for (int r = threadIdx.x; r < NPRE; r += 1024) {
        unsigned long long comp = sh[r];
        unsigned j = 0xFFFFFFFFu - (unsigned)(comp & 0xFFFFFFFFull);
        if (j >= NA) j = NA - 1;
        g_bsort[n][r] = g_boxes[(size_t)n * NA + j];
    }
}

// ---------------- NMS masks ----------------
__global__ __launch_bounds__(64) void masks_k() {
    int n = blockIdx.z, ci = blockIdx.y, cj = blockIdx.x;
    int t = threadIdx.x;
    int i = ci * 64 + t;
    if (cj < ci) { g_masks[n][i][cj] = 0ull; return; }
    __shared__ float4 bj[64];
    int jg = cj * 64 + t;
    bj[t] = (jg < NPRE) ? g_bsort[n][jg] : make_float4(0.f, 0.f, 0.f, 0.f);
    __syncthreads();
    if (i >= NPRE) { g_masks[n][i][cj] = 0ull; return; }
    float4 bi = g_bsort[n][i];
    float areai = (bi.z - bi.x) * (bi.w - bi.y);
    unsigned long long m = 0ull;
    int jbase = cj * 64;
    #pragma unroll 8
    for (int jj = 0; jj < 64; jj++) {
        int jgl = jbase + jj;
        if (jgl > i && jgl < NPRE) {
            float4 bb = bj[jj];
            float ty1 = fmaxf(bi.x, bb.x), tx1 = fmaxf(bi.y, bb.y);
            float ty2 = fminf(bi.z, bb.z), tx2 = fminf(bi.w, bb.w);
            float ihh = fmaxf(ty2 - ty1, 0.f), iww = fmaxf(tx2 - tx1, 0.f);
            float inter = ihh * iww;
            float areaj = (bb.z - bb.x) * (bb.w - bb.y);
            float iou = inter / (areai + areaj - inter + 1e-10f);
            if (iou > 0.7f) m |= (1ull << jj);
        }
    }
    g_masks[n][i][cj] = m;
}

// ---------------- single-warp NMS reduction (depth-8 prefetch, R8 version) + emit ----------------
__global__ __launch_bounds__(32) void nms_emit_k(float* __restrict__ dout) {
    int n = blockIdx.x;
    int l = threadIdx.x;
    int c0 = l, c1 = l + 32, c2 = l + 64;
    bool v2 = c2 < NCHUNK;
    unsigned long long rv0 = 0, rv1 = 0, rv2 = 0;
    unsigned long long b0[8], b1[8], b2[8];
    #pragma unroll
    for (int s = 0; s < 8; s++) {
        b0[s] = g_masks[n][s][c0];
        b1[s] = g_masks[n][s][c1];
        b2[s] = v2 ? g_masks[n][s][c2] : 0ull;
    }
    for (int ib = 0; ib < NPRE; ib += 8) {
        #pragma unroll
        for (int s = 0; s < 8; s++) {
            int i = ib + s;
            unsigned long long cm0 = b0[s], cm1 = b1[s], cm2 = b2[s];
            if (i + 8 < NPRE) {
                b0[s] = g_masks[n][i + 8][c0];
                b1[s] = g_masks[n][i + 8][c1];
                b2[s] = v2 ? g_masks[n][i + 8][c2] : 0ull;
            }
            int ch = i >> 6, slot = ch >> 5, src = ch & 31;
            unsigned long long rsel = (slot == 0) ? rv0 : ((slot == 1) ? rv1 : rv2);
            unsigned long long v = __shfl_sync(0xFFFFFFFFu, rsel, src);
            if (!((v >> (i & 63)) & 1ull)) { rv0 |= cm0; rv1 |= cm1; rv2 |= cm2; }
        }
    }
    __shared__ unsigned long long remv[96];
    remv[l] = rv0; remv[l + 32] = rv1;
    if (v2) remv[l + 64] = rv2;
    __syncwarp();
    float* rind = dout + RIND_OFF + n * NPOST;
    for (int q = l; q < NPOST; q += 32) rind[q] = (float)n;
    if (l == 0) {
        float4* rois = (float4*)(dout + ROIS_OFF) + n * NPOST;
        int r = 0;
        for (int i = 0; i < NPRE && r < NPOST; i++)
            if (((remv[i >> 6] >> (i & 63)) & 1ull) == 0ull) rois[r++] = g_bsort[n][i];
        for (int i = 0; i < NPRE && r < NPOST; i++)
            if (((remv[i >> 6] >> (i & 63)) & 1ull) != 0ull) rois[r++] = g_bsort[n][i];
    }
}

// ---------------- launch ----------------
extern "C" void kernel_launch(void* const* d_in, const int* in_sizes, int n_in,
                              void* d_out, int out_size) {
    const float* x  = (const float*)d_in[0];
    const float* W1 = (const float*)d_in[1];
    const float* b1 = (const float*)d_in[2];
    const float* Ws = (const float*)d_in[3];
    const float* bs = (const float*)d_in[4];
    const float* Wl = (const float*)d_in[5];
    const float* bl = (const float*)d_in[6];
    const int* ih   = (const int*)d_in[7];
    const int* iw   = (const int*)d_in[8];
    float* out = (float*)d_out;

    cudaFuncSetAttribute(sort_k, cudaFuncAttributeMaxDynamicSharedMemorySize, SORTN * 8);
    cudaFuncSetAttribute(conv_mma_k, cudaFuncAttributeMaxDynamicSharedMemorySize, CONV_SMEM);

    init_k<<<(N_BATCH * SORTN + 255) / 256, 256>>>();
    xzero_k<<<(int)(((size_t)N_BATCH * 2 * PADPX * CIN / 4 + 255) / 256), 256>>>();
    wsplit_k<<<(9 * CIN * CIN + 255) / 256, 256>>>(W1);
    xsplit_k<<<dim3(64, 8, 4), 256>>>(x);
    conv_mma_k<<<dim3(64, 4, 4), 256, CONV_SMEM>>>(b1);
    heads_k<<<dim3(64, 4), 256>>>(Wl, bl, Ws, bs, out);
    anchors_k<<<(NA + 255) / 256, 256>>>(out);
    boxes_k<<<(N_BATCH * NA + 255) / 256, 256>>>(out, ih, iw);
    select_k<<<N_BATCH, 1024>>>();
    compact_k<<<(N_BATCH * NA + 255) / 256, 256>>>();
    sort_k<<<N_BATCH, 1024, SORTN * 8>>>();
    masks_k<<<dim3(NCHUNK, NCHUNK, N_BATCH), 64>>>();
    nms_emit_k<<<N_BATCH, 32>>>(out);
}

// round 14
// speedup vs baseline: 1.9556x; 1.2743x over previous
#include <cuda_runtime.h>
#include <cuda_fp16.h>
#include <math.h>
#include <stdint.h>

#define N_BATCH 4
#define CIN     512
#define COUT    512
#define HWPIX   4096
#define NA      36864
#define NPRE    6000
#define NPOST   300
#define NCHUNK  94
#define NPAD    6016
#define SORTN   8192
#define PADPX   4356      // 66*66
#define NTILE   1024      // 32x32 winograd tiles per image

#define LOCS_OFF   0
#define SCORES_OFF 589824
#define ROIS_OFF   884736
#define RIND_OFF   889536
#define ANCH_OFF   890736

// wino_mma smem: 128 bias pad + 2 stages of (A 64x144B + B 128x144B) + master 32x256 floats
#define STAGE_BYTES  27648
#define MASTER_OFF_F (128 + 2 * STAGE_BYTES / 4)
#define CONV_SMEM    88576

// ---------------- scratch ----------------
__device__ float               g_xt[(size_t)N_BATCH * PADPX * CIN];            // padded transposed x (fp32)
__device__ __half              g_V[(size_t)2 * N_BATCH * 16 * NTILE * CIN];    // V splits [sp][n][u][tile][ic]
__device__ __half              g_U[(size_t)2 * 16 * COUT * CIN];               // U splits [sp][u][oc][ic]
__device__ float               g_M[(size_t)16 * N_BATCH * NTILE * COUT];       // transform-domain product
__device__ float               g_hp[(size_t)N_BATCH * HWPIX * COUT];           // conv output, px-major [n][px][oc]
__device__ float               g_fg[N_BATCH * NA];
__device__ float4              g_boxes[N_BATCH * NA];
__device__ unsigned            g_keys[N_BATCH * NA];
__device__ unsigned            g_cut[N_BATCH];
__device__ int                 g_cnt[N_BATCH];
__device__ unsigned long long  g_sel[N_BATCH][SORTN];
__device__ float4              g_bsort[N_BATCH][NPAD];
__device__ unsigned long long  g_masks[N_BATCH][NPAD][NCHUNK];

// ---------------- helpers ----------------
__device__ __forceinline__ uint32_t smem_u32(const void* p) {
    uint32_t a;
    asm("{ .reg .u64 t; cvta.to.shared.u64 t, %1; cvt.u32.u64 %0, t; }" : "=r"(a) : "l"(p));
    return a;
}
__device__ __forceinline__ unsigned f2key(float f) {
    unsigned u = __float_as_uint(f);
    return (u & 0x80000000u) ? ~u : (u | 0x80000000u);
}
__device__ __forceinline__ void anchor_base(int a, float* out) {
    const double ratios[3] = {0.5, 1.0, 2.0};
    const double scales[3] = {8.0, 16.0, 32.0};
    int ri = a / 3, si = a % 3;
    double h = 16.0 * scales[si] * sqrt(ratios[ri]);
    double w = 16.0 * scales[si] * sqrt(1.0 / ratios[ri]);
    out[0] = (float)(8.0 - h * 0.5);
    out[1] = (float)(8.0 - w * 0.5);
    out[2] = (float)(8.0 + h * 0.5);
    out[3] = (float)(8.0 + w * 0.5);
}

// ---------------- init ----------------
__global__ void init_k() {
    int idx = blockIdx.x * 256 + threadIdx.x;
    if (idx < N_BATCH) g_cnt[idx] = 0;
    if (idx < N_BATCH * SORTN) (&g_sel[0][0])[idx] = 0ull;
}

__global__ void xtzero_k() {
    size_t idx = (size_t)blockIdx.x * 256 + threadIdx.x;
    size_t total = (size_t)N_BATCH * PADPX * CIN / 2;   // u64 chunks
    if (idx < total) ((unsigned long long*)g_xt)[idx] = 0ull;
}

// transpose x -> g_xt[n][prow*66+pcol][ic], interior at +1 offset (fp32)
__global__ __launch_bounds__(256) void xt_k(const float* __restrict__ x) {
    __shared__ float s[64][65];
    int row = blockIdx.x, ic0 = blockIdx.y * 64, n = blockIdx.z;
    int tid = threadIdx.x;
    #pragma unroll
    for (int k = 0; k < 16; k++) {
        int idx = tid + k * 256;
        int ic_l = idx >> 6, p = idx & 63;
        s[ic_l][p] = x[((size_t)(n * CIN + ic0 + ic_l) << 12) + row * 64 + p];
    }
    __syncthreads();
    #pragma unroll
    for (int k = 0; k < 16; k++) {
        int idx = tid + k * 256;
        int p = idx >> 6, ic_l = idx & 63;
        int prow = (row + 1) * 66 + (p + 1);
        g_xt[((size_t)n * PADPX + prow) * CIN + ic0 + ic_l] = s[ic_l][p];
    }
}

// weight transform U = G g G^T, split to fp16 hi / lo*4096 -> g_U[sp][u][oc][ic]
__global__ void uwino_k(const float* __restrict__ W1) {
    int e = blockIdx.x * 256 + threadIdx.x;
    if (e >= COUT * CIN) return;
    int oc = e >> 9, ic = e & 511;
    float g[3][3];
    #pragma unroll
    for (int t = 0; t < 9; t++) g[t / 3][t % 3] = W1[((size_t)oc * CIN + ic) * 9 + t];
    float r[4][3];
    #pragma unroll
    for (int k = 0; k < 3; k++) {
        r[0][k] = g[0][k];
        r[1][k] = 0.5f * (g[0][k] + g[1][k] + g[2][k]);
        r[2][k] = 0.5f * (g[0][k] - g[1][k] + g[2][k]);
        r[3][k] = g[2][k];
    }
    #pragma unroll
    for (int i = 0; i < 4; i++) {
        float U0 = r[i][0];
        float U1 = 0.5f * (r[i][0] + r[i][1] + r[i][2]);
        float U2 = 0.5f * (r[i][0] - r[i][1] + r[i][2]);
        float U3 = r[i][2];
        float Uv[4] = {U0, U1, U2, U3};
        #pragma unroll
        for (int j = 0; j < 4; j++) {
            int u = i * 4 + j;
            __half hi = __float2half(Uv[j]);
            float lo = (Uv[j] - __half2float(hi)) * 4096.f;
            size_t o = ((size_t)u * COUT + oc) * CIN + ic;
            g_U[o] = hi;
            g_U[o + (size_t)16 * COUT * CIN] = __float2half(lo);
        }
    }
}

// input transform V = B^T d B, split -> g_V[sp][n][u][tile][ic]
// grid (1024 tiles, 2 ic-chunks, 4 n), 256 threads = ic within chunk
__global__ __launch_bounds__(256) void vwino_k() {
    int tile = blockIdx.x, n = blockIdx.z;
    int ic = blockIdx.y * 256 + threadIdx.x;
    int ty = tile >> 5, tx = tile & 31;
    float d[4][4];
    #pragma unroll
    for (int i = 0; i < 4; i++)
        #pragma unroll
        for (int j = 0; j < 4; j++)
            d[i][j] = g_xt[((size_t)n * PADPX + (2 * ty + i) * 66 + 2 * tx + j) * CIN + ic];
    float t[4][4];
    #pragma unroll
    for (int j = 0; j < 4; j++) {
        t[0][j] = d[0][j] - d[2][j];
        t[1][j] = d[1][j] + d[2][j];
        t[2][j] = d[2][j] - d[1][j];
        t[3][j] = d[1][j] - d[3][j];
    }
    #pragma unroll
    for (int i = 0; i < 4; i++) {
        float V0 = t[i][0] - t[i][2];
        float V1 = t[i][1] + t[i][2];
        float V2 = t[i][2] - t[i][1];
        float V3 = t[i][1] - t[i][3];
        float Vv[4] = {V0, V1, V2, V3};
        #pragma unroll
        for (int j = 0; j < 4; j++) {
            int u = i * 4 + j;
            __half hi = __float2half(Vv[j]);
            float lo = (Vv[j] - __half2float(hi)) * 4096.f;
            size_t o = (((size_t)n * 16 + u) * NTILE + tile) * CIN + ic;
            g_V[o] = hi;
            g_V[o + (size_t)N_BATCH * 16 * NTILE * CIN] = __float2half(lo);
        }
    }
}

// ---------------- winograd-domain GEMM via mma.sync fp16 3-term ----------------
// grid (16 m-blocks, 4 oc-blocks, 64 = u*4+n), 256 threads (8 warps 2m x 4n), 2 CTAs/SM.
// Block tile 64 tiles x 128 oc; 24 iters: 8 hh + 8 Vhi*Ulo + 8 Vlo*Uhi (K=64 ic each).
__device__ __forceinline__ void wino_issue(int iter, uint32_t dstbase,
                                           int tid, int mb, int ocb, int u, int n) {
    int term = iter >> 3;
    int icc = (iter & 7) * 64;
    int sAs = (term == 2) ? 1 : 0;
    int sBs = (term == 1) ? 1 : 0;
    const __half* vbase = g_V + (size_t)sAs * N_BATCH * 16 * NTILE * CIN
                        + (((size_t)n * 16 + u) * NTILE + mb * 64) * CIN + icc;
    #pragma unroll
    for (int r = 0; r < 2; r++) {
        int idx = tid + r * 256;
        int arow = idx >> 3, q = idx & 7;
        const __half* src = vbase + (size_t)arow * CIN + q * 8;
        uint32_t dst = dstbase + (uint32_t)(arow * 144 + q * 16);
        asm volatile("cp.async.cg.shared.global [%0], [%1], 16;" :: "r"(dst), "l"(src));
    }
    const __half* ubase = g_U + (size_t)sBs * 16 * COUT * CIN
                        + ((size_t)u * COUT + ocb * 128) * CIN + icc;
    #pragma unroll
    for (int r = 0; r < 4; r++) {
        int idx = tid + r * 256;
        int brow = idx >> 3, q = idx & 7;
        const __half* src = ubase + (size_t)brow * CIN + q * 8;
        uint32_t dst = dstbase + (uint32_t)(9216 + brow * 144 + q * 16);
        asm volatile("cp.async.cg.shared.global [%0], [%1], 16;" :: "r"(dst), "l"(src));
    }
}

__global__ __launch_bounds__(256, 2) void wino_mma_k() {
    extern __shared__ float dyn[];
    char* sStage = (char*)(dyn + 128);
    float* sMaster = dyn + MASTER_OFF_F;
    uint32_t bufu = smem_u32(sStage);
    int tid = threadIdx.x, lane = tid & 31, warp = tid >> 5;
    int g = lane >> 2, tig = lane & 3;
    int warpm = warp & 1, warpn = warp >> 1;
    int mb = blockIdx.x, ocb = blockIdx.y;
    int u = blockIdx.z >> 2, n = blockIdx.z & 3;

    float work[2][4][4] = {};

    wino_issue(0, bufu, tid, mb, ocb, u, n);
    asm volatile("cp.async.commit_group;" ::: "memory");

    for (int iter = 0; iter < 24; iter++) {
        asm volatile("cp.async.wait_group 0;" ::: "memory");
        __syncthreads();
        if (iter + 1 < 24) {
            wino_issue(iter + 1, bufu + (uint32_t)((iter + 1) & 1) * STAGE_BYTES,
                       tid, mb, ocb, u, n);
            asm volatile("cp.async.commit_group;" ::: "memory");
        }
        const uint32_t* sA = (const uint32_t*)(sStage + (iter & 1) * STAGE_BYTES);
        const uint32_t* sB = sA + 2304;

        #pragma unroll
        for (int ks = 0; ks < 4; ks++) {
            int kw = ks * 8;
            uint32_t a[2][4];
            #pragma unroll
            for (int mt = 0; mt < 2; mt++) {
                int base = warpm * 32 + mt * 16;
                a[mt][0] = sA[(base + g) * 36 + kw + tig];
                a[mt][1] = sA[(base + g + 8) * 36 + kw + tig];
                a[mt][2] = sA[(base + g) * 36 + kw + 4 + tig];
                a[mt][3] = sA[(base + g + 8) * 36 + kw + 4 + tig];
            }
            #pragma unroll
            for (int nt = 0; nt < 4; nt++) {
                int col = warpn * 32 + nt * 8 + g;
                uint32_t b0 = sB[col * 36 + kw + tig];
                uint32_t b1 = sB[col * 36 + kw + 4 + tig];
                #pragma unroll
                for (int mt = 0; mt < 2; mt++) {
                    asm volatile(
                        "mma.sync.aligned.m16n8k16.row.col.f32.f16.f16.f32 "
                        "{%0,%1,%2,%3}, {%4,%5,%6,%7}, {%8,%9}, {%0,%1,%2,%3};"
                        : "+f"(work[mt][nt][0]), "+f"(work[mt][nt][1]),
                          "+f"(work[mt][nt][2]), "+f"(work[mt][nt][3])
                        : "r"(a[mt][0]), "r"(a[mt][1]), "r"(a[mt][2]), "r"(a[mt][3]),
                          "r"(b0), "r"(b1));
                }
            }
        }
        if ((iter & 3) == 3) {
            bool first = (iter == 3);
            bool corr = (iter >= 8);
            float sc = corr ? (1.f / 4096.f) : 1.f;
            #pragma unroll
            for (int mt = 0; mt < 2; mt++)
                #pragma unroll
                for (int nt = 0; nt < 4; nt++)
                    #pragma unroll
                    for (int q = 0; q < 4; q++) {
                        int e = ((mt * 4) + nt) * 4 + q;
                        float w = work[mt][nt][q] * sc;
                        if (first) sMaster[e * 256 + tid] = w;
                        else       sMaster[e * 256 + tid] += w;
                        work[mt][nt][q] = 0.f;
                    }
        }
    }
    __syncthreads();

    size_t mbase = ((size_t)(u * 4 + n) * NTILE) * COUT;
    #pragma unroll
    for (int mt = 0; mt < 2; mt++) {
        int tile = mb * 64 + warpm * 32 + mt * 16 + g;
        #pragma unroll
        for (int nt = 0; nt < 4; nt++) {
            int oc = ocb * 128 + warpn * 32 + nt * 8 + 2 * tig;
            int e = ((mt * 4) + nt) * 4;
            g_M[mbase + (size_t)tile * COUT + oc]           = sMaster[(e + 0) * 256 + tid];
            g_M[mbase + (size_t)tile * COUT + oc + 1]       = sMaster[(e + 1) * 256 + tid];
            g_M[mbase + (size_t)(tile + 8) * COUT + oc]     = sMaster[(e + 2) * 256 + tid];
            g_M[mbase + (size_t)(tile + 8) * COUT + oc + 1] = sMaster[(e + 3) * 256 + tid];
        }
    }
}

// output transform Y = A^T M A + bias, relu -> g_hp[n][px][oc]
// grid (1024 tiles, 4 n), 512 threads = oc
__global__ __launch_bounds__(512) void owino_k(const float* __restrict__ bias) {
    int tile = blockIdx.x, n = blockIdx.y;
    int oc = threadIdx.x;
    int ty = tile >> 5, tx = tile & 31;
    float m[16];
    #pragma unroll
    for (int u = 0; u < 16; u++)
        m[u] = g_M[((size_t)(u * 4 + n) * NTILE + tile) * COUT + oc];
    float t[2][4];
    #pragma unroll
    for (int j = 0; j < 4; j++) {
        t[0][j] = m[0 * 4 + j] + m[1 * 4 + j] + m[2 * 4 + j];
        t[1][j] = m[1 * 4 + j] - m[2 * 4 + j] - m[3 * 4 + j];
    }
    float bv = bias[oc];
    #pragma unroll
    for (int i = 0; i < 2; i++) {
        float y0 = t[i][0] + t[i][1] + t[i][2] + bv;
        float y1 = t[i][1] - t[i][2] - t[i][3] + bv;
        int py = 2 * ty + i;
        size_t b = ((size_t)n * HWPIX + py * 64 + 2 * tx) * COUT + oc;
        g_hp[b]        = fmaxf(y0, 0.f);
        g_hp[b + COUT] = fmaxf(y1, 0.f);
    }
}

// ---------------- fused 1x1 heads + fg softmax (reads px-major g_hp) ----------------
__global__ __launch_bounds__(256) void heads_k(const float* __restrict__ Wl,
                                               const float* __restrict__ bl,
                                               const float* __restrict__ Ws,
                                               const float* __restrict__ bs,
                                               float* __restrict__ dout) {
    int n = blockIdx.y;
    int p0 = blockIdx.x * 64;
    int tid = threadIdx.x;
    int pxg = tid & 15, cg = tid >> 4;
    int px0 = pxg * 4, c0 = cg * 4;

    __shared__ float sH[64][65];
    __shared__ float sWc[64][64];

    float acc[4][4] = {};

    for (int icc = 0; icc < CIN; icc += 64) {
        for (int idx = tid; idx < 4096; idx += 256) {
            int p = idx >> 6, ic = idx & 63;
            sH[ic][p] = g_hp[((size_t)n * HWPIX + p0 + p) * COUT + icc + ic];
        }
        for (int idx = tid; idx < 4096; idx += 256) {
            int ic = idx >> 6, c = idx & 63;
            float w = 0.f;
            if (c < 36)      w = Wl[(size_t)c * CIN + icc + ic];
            else if (c < 54) w = Ws[(size_t)(c - 36) * CIN + icc + ic];
            sWc[ic][c] = w;
        }
        __syncthreads();
        #pragma unroll 16
        for (int ic = 0; ic < 64; ic++) {
            float w0 = sWc[ic][c0 + 0], w1 = sWc[ic][c0 + 1];
            float w2 = sWc[ic][c0 + 2], w3 = sWc[ic][c0 + 3];
            float v0 = sH[ic][px0 + 0], v1 = sH[ic][px0 + 1];
            float v2 = sH[ic][px0 + 2], v3 = sH[ic][px0 + 3];
            acc[0][0] += w0 * v0; acc[0][1] += w0 * v1; acc[0][2] += w0 * v2; acc[0][3] += w0 * v3;
            acc[1][0] += w1 * v0; acc[1][1] += w1 * v1; acc[1][2] += w1 * v2; acc[1][3] += w1 * v3;
            acc[2][0] += w2 * v0; acc[2][1] += w2 * v1; acc[2][2] += w2 * v2; acc[2][3] += w2 * v3;
            acc[3][0] += w3 * v0; acc[3][1] += w3 * v1; acc[3][2] += w3 * v2; acc[3][3] += w3 * v3;
        }
        __syncthreads();
    }

    float val[4][4];
    #pragma unroll
    for (int ci = 0; ci < 4; ci++) {
        int cc = c0 + ci;
        float bv = (cc < 36) ? bl[cc] : ((cc < 54) ? bs[cc - 36] : 0.f);
        #pragma unroll
        for (int pi = 0; pi < 4; pi++) val[ci][pi] = acc[ci][pi] + bv;
    }
    #pragma unroll
    for (int ci = 0; ci < 4; ci++) {
        int cc = c0 + ci;
        #pragma unroll
        for (int pi = 0; pi < 4; pi++) {
            int p = p0 + px0 + pi;
            if (cc < 36)
                dout[LOCS_OFF + (size_t)n * 147456 + (size_t)p * 36 + cc] = val[ci][pi];
            else if (cc < 54)
                dout[SCORES_OFF + (size_t)n * 73728 + (size_t)p * 18 + (cc - 36)] = val[ci][pi];
        }
    }
    if (c0 >= 36 && c0 < 54) {
        #pragma unroll
        for (int pr = 0; pr < 2; pr++) {
            int ce = c0 + 2 * pr;
            if (ce + 1 < 54) {
                int a = (ce - 36) >> 1;
                #pragma unroll
                for (int pi = 0; pi < 4; pi++) {
                    float d = val[2 * pr + 1][pi] - val[2 * pr][pi];
                    float fg = 1.f / (1.f + expf(-d));
                    g_fg[n * NA + (p0 + px0 + pi) * 9 + a] = fg;
                }
            }
        }
    }
}

// ---------------- anchors ----------------
__global__ void anchors_k(float* __restrict__ dout) {
    int j = blockIdx.x * 256 + threadIdx.x;
    if (j >= NA) return;
    int p = j / 9, a = j % 9;
    int y = p >> 6, xx = p & 63;
    float ab[4];
    anchor_base(a, ab);
    float* o = dout + ANCH_OFF + (size_t)j * 4;
    o[0] = y * 16.f + ab[0];
    o[1] = xx * 16.f + ab[1];
    o[2] = y * 16.f + ab[2];
    o[3] = xx * 16.f + ab[3];
}

// ---------------- loc2bbox + clip + min-size + key ----------------
__global__ void boxes_k(const float* __restrict__ dout,
                        const int* __restrict__ pih, const int* __restrict__ piw) {
    int idx = blockIdx.x * 256 + threadIdx.x;
    if (idx >= N_BATCH * NA) return;
    int n = idx / NA, j = idx - n * NA;
    int p = j / 9, a = j - p * 9;
    int y = p >> 6, xx = p & 63;
    float ab[4];
    anchor_base(a, ab);
    float a0 = y * 16.f + ab[0], a1 = xx * 16.f + ab[1];
    float a2 = y * 16.f + ab[2], a3 = xx * 16.f + ab[3];

    const float* loc = dout + LOCS_OFF + (size_t)n * 147456 + (size_t)j * 4;
    float dy = loc[0], dx = loc[1], dh = loc[2], dw = loc[3];

    float src_h = a2 - a0, src_w = a3 - a1;
    float ctr_y = a0 + 0.5f * src_h, ctr_x = a1 + 0.5f * src_w;
    float cy = dy * src_h + ctr_y;
    float cx = dx * src_w + ctr_x;
    float hh = expf(dh) * src_h;
    float ww = expf(dw) * src_w;

    float fh = (float)(*pih), fw = (float)(*piw);
    float y1 = fminf(fmaxf(cy - 0.5f * hh, 0.f), fh);
    float y2 = fminf(fmaxf(cy + 0.5f * hh, 0.f), fh);
    float x1 = fminf(fmaxf(cx - 0.5f * ww, 0.f), fw);
    float x2 = fminf(fmaxf(cx + 0.5f * ww, 0.f), fw);

    bool valid = ((y2 - y1) >= 16.f) && ((x2 - x1) >= 16.f);
    float sc = valid ? g_fg[idx] : -INFINITY;

    g_boxes[idx] = make_float4(y1, x1, y2, x2);
    g_keys[idx] = f2key(sc);
}

// ---------------- radix select ----------------
__global__ __launch_bounds__(1024) void select_k() {
    int n = blockIdx.x;
    const unsigned* keys = g_keys + (size_t)n * NA;
    __shared__ unsigned hist[256];
    __shared__ unsigned sprefix;
    __shared__ int srem;
    if (threadIdx.x == 0) { sprefix = 0u; srem = NPRE; }
    __syncthreads();
    for (int pass = 0; pass < 4; pass++) {
        for (int b = threadIdx.x; b < 256; b += 1024) hist[b] = 0u;
        __syncthreads();
        int shift = 24 - 8 * pass;
        unsigned maskhi = pass ? (0xFFFFFFFFu << (32 - 8 * pass)) : 0u;
        unsigned pref = sprefix;
        for (int i = threadIdx.x; i < NA; i += 1024) {
            unsigned k = keys[i];
            if ((k & maskhi) == pref) atomicAdd(&hist[(k >> shift) & 0xFF], 1u);
        }
        __syncthreads();
        if (threadIdx.x == 0) {
            unsigned cum = 0;
            int rem = srem;
            for (int b = 255; b >= 0; b--) {
                cum += hist[b];
                if ((int)cum >= rem) {
                    srem = rem - (int)(cum - hist[b]);
                    sprefix = pref | ((unsigned)b << shift);
                    break;
                }
            }
        }
        __syncthreads();
    }
    if (threadIdx.x == 0) g_cut[n] = sprefix;
}

// ---------------- compact ----------------
__global__ void compact_k() {
    int idx = blockIdx.x * 256 + threadIdx.x;
    if (idx >= N_BATCH * NA) return;
    int n = idx / NA;
    unsigned k = g_keys[idx];
    if (k >= g_cut[n]) {
        int pos = atomicAdd(&g_cnt[n], 1);
        if (pos < SORTN) {
            unsigned j = (unsigned)(idx - n * NA);
            g_sel[n][pos] = ((unsigned long long)k << 32) | (0xFFFFFFFFu - j);
        }
    }
}

// ---------------- bitonic sort + gather ----------------
__global__ __launch_bounds__(1024) void sort_k() {
    int n = blockIdx.x;
    extern __shared__ unsigned long long sh[];
    for (int i = threadIdx.x; i < SORTN; i += 1024) sh[i] = g_sel[n][i];
    __syncthreads();
    for (int k = 2; k <= SORTN; k <<= 1) {
        for (int j = k >> 1; j > 0; j >>= 1) {
            for (int i = threadIdx.x; i < SORTN; i += 1024) {
                int ixj = i ^ j;
                if (ixj > i) {
                    unsigned long long a = sh[i], b = sh[ixj];
                    bool up = (i & k) == 0;
                    if (up ? (a < b) : (a > b)) { sh[i] = b; sh[ixj] = a; }
                }
            }
            __syncthreads();
        }
    }
    for (int r = threadIdx.x; r < NPRE; r += 1024) {
        unsigned long long comp = sh[r];
        unsigned j = 0xFFFFFFFFu - (unsigned)(comp & 0xFFFFFFFFull);
        if (j >= NA) j = NA - 1;
        g_bsort[n][r] = g_boxes[(size_t)n * NA + j];
    }
}

// ---------------- NMS masks ----------------
__global__ __launch_bounds__(64) void masks_k() {
    int n = blockIdx.z, ci = blockIdx.y, cj = blockIdx.x;
    int t = threadIdx.x;
    int i = ci * 64 + t;
    if (cj < ci) { g_masks[n][i][cj] = 0ull; return; }
    __shared__ float4 bj[64];
    int jg = cj * 64 + t;
    bj[t] = (jg < NPRE) ? g_bsort[n][jg] : make_float4(0.f, 0.f, 0.f, 0.f);
    __syncthreads();
    if (i >= NPRE) { g_masks[n][i][cj] = 0ull; return; }
    float4 bi = g_bsort[n][i];
    float areai = (bi.z - bi.x) * (bi.w - bi.y);
    unsigned long long m = 0ull;
    int jbase = cj * 64;
    #pragma unroll 8
    for (int jj = 0; jj < 64; jj++) {
        int jgl = jbase + jj;
        if (jgl > i && jgl < NPRE) {
            float4 bb = bj[jj];
            float ty1 = fmaxf(bi.x, bb.x), tx1 = fmaxf(bi.y, bb.y);
            float ty2 = fminf(bi.z, bb.z), tx2 = fminf(bi.w, bb.w);
            float ihh = fmaxf(ty2 - ty1, 0.f), iww = fmaxf(tx2 - tx1, 0.f);
            float inter = ihh * iww;
            float areaj = (bb.z - bb.x) * (bb.w - bb.y);
            float iou = inter / (areai + areaj - inter + 1e-10f);
            if (iou > 0.7f) m |= (1ull << jj);
        }
    }
    g_masks[n][i][cj] = m;
}

// ---------------- single-warp NMS reduction (depth-8 prefetch, R8 version) + emit ----------------
__global__ __launch_bounds__(32) void nms_emit_k(float* __restrict__ dout) {
    int n = blockIdx.x;
    int l = threadIdx.x;
    int c0 = l, c1 = l + 32, c2 = l + 64;
    bool v2 = c2 < NCHUNK;
    unsigned long long rv0 = 0, rv1 = 0, rv2 = 0;
    unsigned long long b0[8], b1[8], b2[8];
    #pragma unroll
    for (int s = 0; s < 8; s++) {
        b0[s] = g_masks[n][s][c0];
        b1[s] = g_masks[n][s][c1];
        b2[s] = v2 ? g_masks[n][s][c2] : 0ull;
    }
    for (int ib = 0; ib < NPRE; ib += 8) {
        #pragma unroll
        for (int s = 0; s < 8; s++) {
            int i = ib + s;
            unsigned long long cm0 = b0[s], cm1 = b1[s], cm2 = b2[s];
            if (i + 8 < NPRE) {
                b0[s] = g_masks[n][i + 8][c0];
                b1[s] = g_masks[n][i + 8][c1];
                b2[s] = v2 ? g_masks[n][i + 8][c2] : 0ull;
            }
            int ch = i >> 6, slot = ch >> 5, src = ch & 31;
            unsigned long long rsel = (slot == 0) ? rv0 : ((slot == 1) ? rv1 : rv2);
            unsigned long long v = __shfl_sync(0xFFFFFFFFu, rsel, src);
            if (!((v >> (i & 63)) & 1ull)) { rv0 |= cm0; rv1 |= cm1; rv2 |= cm2; }
        }
    }
    __shared__ unsigned long long remv[96];
    remv[l] = rv0; remv[l + 32] = rv1;
    if (v2) remv[l + 64] = rv2;
    __syncwarp();
    float* rind = dout + RIND_OFF + n * NPOST;
    for (int q = l; q < NPOST; q += 32) rind[q] = (float)n;
    if (l == 0) {
        float4* rois = (float4*)(dout + ROIS_OFF) + n * NPOST;
        int r = 0;
        for (int i = 0; i < NPRE && r < NPOST; i++)
            if (((remv[i >> 6] >> (i & 63)) & 1ull) == 0ull) rois[r++] = g_bsort[n][i];
        for (int i = 0; i < NPRE && r < NPOST; i++)
            if (((remv[i >> 6] >> (i & 63)) & 1ull) != 0ull) rois[r++] = g_bsort[n][i];
    }
}

// ---------------- launch ----------------
extern "C" void kernel_launch(void* const* d_in, const int* in_sizes, int n_in,
                              void* d_out, int out_size) {
    const float* x  = (const float*)d_in[0];
    const float* W1 = (const float*)d_in[1];
    const float* b1 = (const float*)d_in[2];
    const float* Ws = (const float*)d_in[3];
    const float* bs = (const float*)d_in[4];
    const float* Wl = (const float*)d_in[5];
    const float* bl = (const float*)d_in[6];
    const int* ih   = (const int*)d_in[7];
    const int* iw   = (const int*)d_in[8];
    float* out = (float*)d_out;

    cudaFuncSetAttribute(sort_k, cudaFuncAttributeMaxDynamicSharedMemorySize, SORTN * 8);
    cudaFuncSetAttribute(wino_mma_k, cudaFuncAttributeMaxDynamicSharedMemorySize, CONV_SMEM);

    init_k<<<(N_BATCH * SORTN + 255) / 256, 256>>>();
    xtzero_k<<<(int)(((size_t)N_BATCH * PADPX * CIN / 2 + 255) / 256), 256>>>();
    xt_k<<<dim3(64, 8, 4), 256>>>(x);
    uwino_k<<<(COUT * CIN + 255) / 256, 256>>>(W1);
    vwino_k<<<dim3(NTILE, 2, 4), 256>>>();
    wino_mma_k<<<dim3(16, 4, 64), 256, CONV_SMEM>>>();
    owino_k<<<dim3(NTILE, 4), 512>>>(b1);
    heads_k<<<dim3(64, 4), 256>>>(Wl, bl, Ws, bs, out);
    anchors_k<<<(NA + 255) / 256, 256>>>(out);
    boxes_k<<<(N_BATCH * NA + 255) / 256, 256>>>(out, ih, iw);
    select_k<<<N_BATCH, 1024>>>();
    compact_k<<<(N_BATCH * NA + 255) / 256, 256>>>();
    sort_k<<<N_BATCH, 1024, SORTN * 8>>>();
    masks_k<<<dim3(NCHUNK, NCHUNK, N_BATCH), 64>>>();
    nms_emit_k<<<N_BATCH, 32>>>(out);
}

// round 15
// speedup vs baseline: 2.1599x; 1.1044x over previous
#include <cuda_runtime.h>
#include <cuda_fp16.h>
#include <math.h>
#include <stdint.h>

#define N_BATCH 4
#define CIN     512
#define COUT    512
#define HWPIX   4096
#define NA      36864
#define NPRE    6000
#define NPOST   300
#define NCHUNK  94
#define NPAD    6016
#define SORTN   8192
#define PADPX   4356      // 66*66
#define NTILE   1024      // 32x32 winograd tiles per image
#define GTILE   4096      // tiles across batch (merged M-dim)

#define LOCS_OFF   0
#define SCORES_OFF 589824
#define ROIS_OFF   884736
#define RIND_OFF   889536
#define ANCH_OFF   890736

#define STAGE_BYTES  27648
#define MASTER_OFF_F (128 + 2 * STAGE_BYTES / 4)
#define CONV_SMEM    88576

// ---------------- scratch ----------------
__device__ float               g_xt[(size_t)N_BATCH * PADPX * CIN];
__device__ __half              g_V[(size_t)2 * 16 * GTILE * CIN];        // [sp][u][gtile][ic]
__device__ __half              g_U[(size_t)2 * 16 * COUT * CIN];        // [sp][u][oc][ic]
__device__ float               g_M[(size_t)16 * GTILE * COUT];          // [u][gtile][oc]
__device__ float               g_hp[(size_t)N_BATCH * HWPIX * COUT];    // [n][px][oc]
__device__ float               g_fg[N_BATCH * NA];
__device__ float4              g_boxes[N_BATCH * NA];
__device__ unsigned            g_keys[N_BATCH * NA];
__device__ unsigned            g_cut[N_BATCH];
__device__ int                 g_cnt[N_BATCH];
__device__ unsigned long long  g_sel[N_BATCH][SORTN];
__device__ float4              g_bsort[N_BATCH][NPAD];
__device__ unsigned long long  g_masks[N_BATCH][NPAD][NCHUNK];

// ---------------- helpers ----------------
__device__ __forceinline__ uint32_t smem_u32(const void* p) {
    uint32_t a;
    asm("{ .reg .u64 t; cvta.to.shared.u64 t, %1; cvt.u32.u64 %0, t; }" : "=r"(a) : "l"(p));
    return a;
}
__device__ __forceinline__ unsigned f2key(float f) {
    unsigned u = __float_as_uint(f);
    return (u & 0x80000000u) ? ~u : (u | 0x80000000u);
}
__device__ __forceinline__ void anchor_base(int a, float* out) {
    const double ratios[3] = {0.5, 1.0, 2.0};
    const double scales[3] = {8.0, 16.0, 32.0};
    int ri = a / 3, si = a % 3;
    double h = 16.0 * scales[si] * sqrt(ratios[ri]);
    double w = 16.0 * scales[si] * sqrt(1.0 / ratios[ri]);
    out[0] = (float)(8.0 - h * 0.5);
    out[1] = (float)(8.0 - w * 0.5);
    out[2] = (float)(8.0 + h * 0.5);
    out[3] = (float)(8.0 + w * 0.5);
}

// ---------------- init ----------------
__global__ void init_k() {
    int idx = blockIdx.x * 256 + threadIdx.x;
    if (idx < N_BATCH) g_cnt[idx] = 0;
    if (idx < N_BATCH * SORTN) (&g_sel[0][0])[idx] = 0ull;
}

// zero only the 1-px border of g_xt (interior fully overwritten by xt_k)
__global__ void xborder_k() {
    int idx = blockIdx.x * 256 + threadIdx.x;
    int total = 260 * 512;               // border pixels x ic, per batch
    if (idx >= total * N_BATCH) return;
    int n = idx / total;
    int r = idx - n * total;
    int b = r >> 9, ic = r & 511;
    int prow;
    if (b < 66)        prow = b;                          // top row
    else if (b < 132)  prow = 65 * 66 + (b - 66);         // bottom row
    else if (b < 196)  prow = (b - 132 + 1) * 66;         // left col rows 1..64
    else               prow = (b - 196 + 1) * 66 + 65;    // right col rows 1..64
    g_xt[((size_t)n * PADPX + prow) * CIN + ic] = 0.f;
}

// transpose x -> g_xt[n][prow*66+pcol][ic], interior at +1 offset (fp32)
__global__ __launch_bounds__(256) void xt_k(const float* __restrict__ x) {
    __shared__ float s[64][65];
    int row = blockIdx.x, ic0 = blockIdx.y * 64, n = blockIdx.z;
    int tid = threadIdx.x;
    #pragma unroll
    for (int k = 0; k < 16; k++) {
        int idx = tid + k * 256;
        int ic_l = idx >> 6, p = idx & 63;
        s[ic_l][p] = x[((size_t)(n * CIN + ic0 + ic_l) << 12) + row * 64 + p];
    }
    __syncthreads();
    #pragma unroll
    for (int k = 0; k < 16; k++) {
        int idx = tid + k * 256;
        int p = idx >> 6, ic_l = idx & 63;
        int prow = (row + 1) * 66 + (p + 1);
        g_xt[((size_t)n * PADPX + prow) * CIN + ic0 + ic_l] = s[ic_l][p];
    }
}

// weight transform U = G g G^T, split fp16 hi / lo*4096
__global__ void uwino_k(const float* __restrict__ W1) {
    int e = blockIdx.x * 256 + threadIdx.x;
    if (e >= COUT * CIN) return;
    int oc = e >> 9, ic = e & 511;
    float g[3][3];
    #pragma unroll
    for (int t = 0; t < 9; t++) g[t / 3][t % 3] = W1[((size_t)oc * CIN + ic) * 9 + t];
    float r[4][3];
    #pragma unroll
    for (int k = 0; k < 3; k++) {
        r[0][k] = g[0][k];
        r[1][k] = 0.5f * (g[0][k] + g[1][k] + g[2][k]);
        r[2][k] = 0.5f * (g[0][k] - g[1][k] + g[2][k]);
        r[3][k] = g[2][k];
    }
    #pragma unroll
    for (int i = 0; i < 4; i++) {
        float U0 = r[i][0];
        float U1 = 0.5f * (r[i][0] + r[i][1] + r[i][2]);
        float U2 = 0.5f * (r[i][0] - r[i][1] + r[i][2]);
        float U3 = r[i][2];
        float Uv[4] = {U0, U1, U2, U3};
        #pragma unroll
        for (int j = 0; j < 4; j++) {
            int u = i * 4 + j;
            __half hi = __float2half(Uv[j]);
            float lo = (Uv[j] - __half2float(hi)) * 4096.f;
            size_t o = ((size_t)u * COUT + oc) * CIN + ic;
            g_U[o] = hi;
            g_U[o + (size_t)16 * COUT * CIN] = __float2half(lo);
        }
    }
}

// input transform V = B^T d B, split -> g_V[sp][u][gtile][ic], gtile = n*1024+tile
__global__ __launch_bounds__(256) void vwino_k() {
    int tile = blockIdx.x, n = blockIdx.z;
    int ic = blockIdx.y * 256 + threadIdx.x;
    int ty = tile >> 5, tx = tile & 31;
    int gtile = n * NTILE + tile;
    float d[4][4];
    #pragma unroll
    for (int i = 0; i < 4; i++)
        #pragma unroll
        for (int j = 0; j < 4; j++)
            d[i][j] = g_xt[((size_t)n * PADPX + (2 * ty + i) * 66 + 2 * tx + j) * CIN + ic];
    float t[4][4];
    #pragma unroll
    for (int j = 0; j < 4; j++) {
        t[0][j] = d[0][j] - d[2][j];
        t[1][j] = d[1][j] + d[2][j];
        t[2][j] = d[2][j] - d[1][j];
        t[3][j] = d[1][j] - d[3][j];
    }
    #pragma unroll
    for (int i = 0; i < 4; i++) {
        float V0 = t[i][0] - t[i][2];
        float V1 = t[i][1] + t[i][2];
        float V2 = t[i][2] - t[i][1];
        float V3 = t[i][1] - t[i][3];
        float Vv[4] = {V0, V1, V2, V3};
        #pragma unroll
        for (int j = 0; j < 4; j++) {
            int u = i * 4 + j;
            __half hi = __float2half(Vv[j]);
            float lo = (Vv[j] - __half2float(hi)) * 4096.f;
            size_t o = ((size_t)u * GTILE + gtile) * CIN + ic;
            g_V[o] = hi;
            g_V[o + (size_t)16 * GTILE * CIN] = __float2half(lo);
        }
    }
}

// ---------------- winograd-domain GEMM (batch-merged M) ----------------
// grid (64 m-blocks, 4 oc-blocks, 16 u), 256 threads (8 warps 2m x 4n), 2 CTAs/SM.
__device__ __forceinline__ void wino_issue(int iter, uint32_t dstbase,
                                           int tid, int mb, int ocb, int u) {
    int term = iter >> 3;
    int icc = (iter & 7) * 64;
    int sAs = (term == 2) ? 1 : 0;
    int sBs = (term == 1) ? 1 : 0;
    const __half* vbase = g_V + (size_t)sAs * 16 * GTILE * CIN
                        + ((size_t)u * GTILE + mb * 64) * CIN + icc;
    #pragma unroll
    for (int r = 0; r < 2; r++) {
        int idx = tid + r * 256;
        int arow = idx >> 3, q = idx & 7;
        const __half* src = vbase + (size_t)arow * CIN + q * 8;
        uint32_t dst = dstbase + (uint32_t)(arow * 144 + q * 16);
        asm volatile("cp.async.cg.shared.global [%0], [%1], 16;" :: "r"(dst), "l"(src));
    }
    const __half* ubase = g_U + (size_t)sBs * 16 * COUT * CIN
                        + ((size_t)u * COUT + ocb * 128) * CIN + icc;
    #pragma unroll
    for (int r = 0; r < 4; r++) {
        int idx = tid + r * 256;
        int brow = idx >> 3, q = idx & 7;
        const __half* src = ubase + (size_t)brow * CIN + q * 8;
        uint32_t dst = dstbase + (uint32_t)(9216 + brow * 144 + q * 16);
        asm volatile("cp.async.cg.shared.global [%0], [%1], 16;" :: "r"(dst), "l"(src));
    }
}

__global__ __launch_bounds__(256, 2) void wino_mma_k() {
    extern __shared__ float dyn[];
    char* sStage = (char*)(dyn + 128);
    float* sMaster = dyn + MASTER_OFF_F;
    uint32_t bufu = smem_u32(sStage);
    int tid = threadIdx.x, lane = tid & 31, warp = tid >> 5;
    int g = lane >> 2, tig = lane & 3;
    int warpm = warp & 1, warpn = warp >> 1;
    int mb = blockIdx.x, ocb = blockIdx.y, u = blockIdx.z;

    float work[2][4][4] = {};

    wino_issue(0, bufu, tid, mb, ocb, u);
    asm volatile("cp.async.commit_group;" ::: "memory");

    for (int iter = 0; iter < 24; iter++) {
        asm volatile("cp.async.wait_group 0;" ::: "memory");
        __syncthreads();
        if (iter + 1 < 24) {
            wino_issue(iter + 1, bufu + (uint32_t)((iter + 1) & 1) * STAGE_BYTES,
                       tid, mb, ocb, u);
            asm volatile("cp.async.commit_group;" ::: "memory");
        }
        const uint32_t* sA = (const uint32_t*)(sStage + (iter & 1) * STAGE_BYTES);
        const uint32_t* sB = sA + 2304;

        #pragma unroll
        for (int ks = 0; ks < 4; ks++) {
            int kw = ks * 8;
            uint32_t a[2][4];
            #pragma unroll
            for (int mt = 0; mt < 2; mt++) {
                int base = warpm * 32 + mt * 16;
                a[mt][0] = sA[(base + g) * 36 + kw + tig];
                a[mt][1] = sA[(base + g + 8) * 36 + kw + tig];
                a[mt][2] = sA[(base + g) * 36 + kw + 4 + tig];
                a[mt][3] = sA[(base + g + 8) * 36 + kw + 4 + tig];
            }
            #pragma unroll
            for (int nt = 0; nt < 4; nt++) {
                int col = warpn * 32 + nt * 8 + g;
                uint32_t b0 = sB[col * 36 + kw + tig];
                uint32_t b1 = sB[col * 36 + kw + 4 + tig];
                #pragma unroll
                for (int mt = 0; mt < 2; mt++) {
                    asm volatile(
                        "mma.sync.aligned.m16n8k16.row.col.f32.f16.f16.f32 "
                        "{%0,%1,%2,%3}, {%4,%5,%6,%7}, {%8,%9}, {%0,%1,%2,%3};"
                        : "+f"(work[mt][nt][0]), "+f"(work[mt][nt][1]),
                          "+f"(work[mt][nt][2]), "+f"(work[mt][nt][3])
                        : "r"(a[mt][0]), "r"(a[mt][1]), "r"(a[mt][2]), "r"(a[mt][3]),
                          "r"(b0), "r"(b1));
                }
            }
        }
        if ((iter & 3) == 3) {
            bool first = (iter == 3);
            bool corr = (iter >= 8);
            float sc = corr ? (1.f / 4096.f) : 1.f;
            #pragma unroll
            for (int mt = 0; mt < 2; mt++)
                #pragma unroll
                for (int nt = 0; nt < 4; nt++)
                    #pragma unroll
                    for (int q = 0; q < 4; q++) {
                        int e = ((mt * 4) + nt) * 4 + q;
                        float w = work[mt][nt][q] * sc;
                        if (first) sMaster[e * 256 + tid] = w;
                        else       sMaster[e * 256 + tid] += w;
                        work[mt][nt][q] = 0.f;
                    }
        }
    }
    __syncthreads();

    size_t mbase = (size_t)u * GTILE * COUT;
    #pragma unroll
    for (int mt = 0; mt < 2; mt++) {
        int tile = mb * 64 + warpm * 32 + mt * 16 + g;
        #pragma unroll
        for (int nt = 0; nt < 4; nt++) {
            int oc = ocb * 128 + warpn * 32 + nt * 8 + 2 * tig;
            int e = ((mt * 4) + nt) * 4;
            g_M[mbase + (size_t)tile * COUT + oc]           = sMaster[(e + 0) * 256 + tid];
            g_M[mbase + (size_t)tile * COUT + oc + 1]       = sMaster[(e + 1) * 256 + tid];
            g_M[mbase + (size_t)(tile + 8) * COUT + oc]     = sMaster[(e + 2) * 256 + tid];
            g_M[mbase + (size_t)(tile + 8) * COUT + oc + 1] = sMaster[(e + 3) * 256 + tid];
        }
    }
}

// output transform Y = A^T M A + bias, relu -> g_hp[n][px][oc]
__global__ __launch_bounds__(512) void owino_k(const float* __restrict__ bias) {
    int tile = blockIdx.x, n = blockIdx.y;
    int oc = threadIdx.x;
    int ty = tile >> 5, tx = tile & 31;
    int gtile = n * NTILE + tile;
    float m[16];
    #pragma unroll
    for (int u = 0; u < 16; u++)
        m[u] = g_M[((size_t)u * GTILE + gtile) * COUT + oc];
    float t[2][4];
    #pragma unroll
    for (int j = 0; j < 4; j++) {
        t[0][j] = m[0 * 4 + j] + m[1 * 4 + j] + m[2 * 4 + j];
        t[1][j] = m[1 * 4 + j] - m[2 * 4 + j] - m[3 * 4 + j];
    }
    float bv = bias[oc];
    #pragma unroll
    for (int i = 0; i < 2; i++) {
        float y0 = t[i][0] + t[i][1] + t[i][2] + bv;
        float y1 = t[i][1] - t[i][2] - t[i][3] + bv;
        int py = 2 * ty + i;
        size_t b = ((size_t)n * HWPIX + py * 64 + 2 * tx) * COUT + oc;
        g_hp[b]        = fmaxf(y0, 0.f);
        g_hp[b + COUT] = fmaxf(y1, 0.f);
    }
}

// ---------------- fused 1x1 heads + fg softmax ----------------
__global__ __launch_bounds__(256) void heads_k(const float* __restrict__ Wl,
                                               const float* __restrict__ bl,
                                               const float* __restrict__ Ws,
                                               const float* __restrict__ bs,
                                               float* __restrict__ dout) {
    int n = blockIdx.y;
    int p0 = blockIdx.x * 64;
    int tid = threadIdx.x;
    int pxg = tid & 15, cg = tid >> 4;
    int px0 = pxg * 4, c0 = cg * 4;

    __shared__ float sH[64][65];
    __shared__ float sWc[64][64];

    float acc[4][4] = {};

    for (int icc = 0; icc < CIN; icc += 64) {
        for (int idx = tid; idx < 4096; idx += 256) {
            int p = idx >> 6, ic = idx & 63;
            sH[ic][p] = g_hp[((size_t)n * HWPIX + p0 + p) * COUT + icc + ic];
        }
        for (int idx = tid; idx < 4096; idx += 256) {
            int ic = idx >> 6, c = idx & 63;
            float w = 0.f;
            if (c < 36)      w = Wl[(size_t)c * CIN + icc + ic];
            else if (c < 54) w = Ws[(size_t)(c - 36) * CIN + icc + ic];
            sWc[ic][c] = w;
        }
        __syncthreads();
        #pragma unroll 16
        for (int ic = 0; ic < 64; ic++) {
            float w0 = sWc[ic][c0 + 0], w1 = sWc[ic][c0 + 1];
            float w2 = sWc[ic][c0 + 2], w3 = sWc[ic][c0 + 3];
            float v0 = sH[ic][px0 + 0], v1 = sH[ic][px0 + 1];
            float v2 = sH[ic][px0 + 2], v3 = sH[ic][px0 + 3];
            acc[0][0] += w0 * v0; acc[0][1] += w0 * v1; acc[0][2] += w0 * v2; acc[0][3] += w0 * v3;
            acc[1][0] += w1 * v0; acc[1][1] += w1 * v1; acc[1][2] += w1 * v2; acc[1][3] += w1 * v3;
            acc[2][0] += w2 * v0; acc[2][1] += w2 * v1; acc[2][2] += w2 * v2; acc[2][3] += w2 * v3;
            acc[3][0] += w3 * v0; acc[3][1] += w3 * v1; acc[3][2] += w3 * v2; acc[3][3] += w3 * v3;
        }
        __syncthreads();
    }

    float val[4][4];
    #pragma unroll
    for (int ci = 0; ci < 4; ci++) {
        int cc = c0 + ci;
        float bv = (cc < 36) ? bl[cc] : ((cc < 54) ? bs[cc - 36] : 0.f);
        #pragma unroll
        for (int pi = 0; pi < 4; pi++) val[ci][pi] = acc[ci][pi] + bv;
    }
    #pragma unroll
    for (int ci = 0; ci < 4; ci++) {
        int cc = c0 + ci;
        #pragma unroll
        for (int pi = 0; pi < 4; pi++) {
            int p = p0 + px0 + pi;
            if (cc < 36)
                dout[LOCS_OFF + (size_t)n * 147456 + (size_t)p * 36 + cc] = val[ci][pi];
            else if (cc < 54)
                dout[SCORES_OFF + (size_t)n * 73728 + (size_t)p * 18 + (cc - 36)] = val[ci][pi];
        }
    }
    if (c0 >= 36 && c0 < 54) {
        #pragma unroll
        for (int pr = 0; pr < 2; pr++) {
            int ce = c0 + 2 * pr;
            if (ce + 1 < 54) {
                int a = (ce - 36) >> 1;
                #pragma unroll
                for (int pi = 0; pi < 4; pi++) {
                    float d = val[2 * pr + 1][pi] - val[2 * pr][pi];
                    float fg = 1.f / (1.f + expf(-d));
                    g_fg[n * NA + (p0 + px0 + pi) * 9 + a] = fg;
                }
            }
        }
    }
}

// ---------------- anchors ----------------
__global__ void anchors_k(float* __restrict__ dout) {
    int j = blockIdx.x * 256 + threadIdx.x;
    if (j >= NA) return;
    int p = j / 9, a = j % 9;
    int y = p >> 6, xx = p & 63;
    float ab[4];
    anchor_base(a, ab);
    float* o = dout + ANCH_OFF + (size_t)j * 4;
    o[0] = y * 16.f + ab[0];
    o[1] = xx * 16.f + ab[1];
    o[2] = y * 16.f + ab[2];
    o[3] = xx * 16.f + ab[3];
}

// ---------------- loc2bbox + clip + min-size + key ----------------
__global__ void boxes_k(const float* __restrict__ dout,
                        const int* __restrict__ pih, const int* __restrict__ piw) {
    int idx = blockIdx.x * 256 + threadIdx.x;
    if (idx >= N_BATCH * NA) return;
    int n = idx / NA, j = idx - n * NA;
    int p = j / 9, a = j - p * 9;
    int y = p >> 6, xx = p & 63;
    float ab[4];
    anchor_base(a, ab);
    float a0 = y * 16.f + ab[0], a1 = xx * 16.f + ab[1];
    float a2 = y * 16.f + ab[2], a3 = xx * 16.f + ab[3];

    const float* loc = dout + LOCS_OFF + (size_t)n * 147456 + (size_t)j * 4;
    float dy = loc[0], dx = loc[1], dh = loc[2], dw = loc[3];

    float src_h = a2 - a0, src_w = a3 - a1;
    float ctr_y = a0 + 0.5f * src_h, ctr_x = a1 + 0.5f * src_w;
    float cy = dy * src_h + ctr_y;
    float cx = dx * src_w + ctr_x;
    float hh = expf(dh) * src_h;
    float ww = expf(dw) * src_w;

    float fh = (float)(*pih), fw = (float)(*piw);
    float y1 = fminf(fmaxf(cy - 0.5f * hh, 0.f), fh);
    float y2 = fminf(fmaxf(cy + 0.5f * hh, 0.f), fh);
    float x1 = fminf(fmaxf(cx - 0.5f * ww, 0.f), fw);
    float x2 = fminf(fmaxf(cx + 0.5f * ww, 0.f), fw);

    bool valid = ((y2 - y1) >= 16.f) && ((x2 - x1) >= 16.f);
    float sc = valid ? g_fg[idx] : -INFINITY;

    g_boxes[idx] = make_float4(y1, x1, y2, x2);
    g_keys[idx] = f2key(sc);
}

// ---------------- radix select ----------------
__global__ __launch_bounds__(1024) void select_k() {
    int n = blockIdx.x;
    const unsigned* keys = g_keys + (size_t)n * NA;
    __shared__ unsigned hist[256];
    __shared__ unsigned sprefix;
    __shared__ int srem;
    if (threadIdx.x == 0) { sprefix = 0u; srem = NPRE; }
    __syncthreads();
    for (int pass = 0; pass < 4; pass++) {
        for (int b = threadIdx.x; b < 256; b += 1024) hist[b] = 0u;
        __syncthreads();
        int shift = 24 - 8 * pass;
        unsigned maskhi = pass ? (0xFFFFFFFFu << (32 - 8 * pass)) : 0u;
        unsigned pref = sprefix;
        for (int i = threadIdx.x; i < NA; i += 1024) {
            unsigned k = keys[i];
            if ((k & maskhi) == pref) atomicAdd(&hist[(k >> shift) & 0xFF], 1u);
        }
        __syncthreads();
        if (threadIdx.x == 0) {
            unsigned cum = 0;
            int rem = srem;
            for (int b = 255; b >= 0; b--) {
                cum += hist[b];
                if ((int)cum >= rem) {
                    srem = rem - (int)(cum - hist[b]);
                    sprefix = pref | ((unsigned)b << shift);
                    break;
                }
            }
        }
        __syncthreads();
    }
    if (threadIdx.x == 0) g_cut[n] = sprefix;
}

// ---------------- compact ----------------
__global__ void compact_k() {
    int idx = blockIdx.x * 256 + threadIdx.x;
    if (idx >= N_BATCH * NA) return;
    int n = idx / NA;
    unsigned k = g_keys[idx];
    if (k >= g_cut[n]) {
        int pos = atomicAdd(&g_cnt[n], 1);
        if (pos < SORTN) {
            unsigned j = (unsigned)(idx - n * NA);
            g_sel[n][pos] = ((unsigned long long)k << 32) | (0xFFFFFFFFu - j);
        }
    }
}

// ---------------- bitonic sort + gather ----------------
__global__ __launch_bounds__(1024) void sort_k() {
    int n = blockIdx.x;
    extern __shared__ unsigned long long sh[];
    for (int i = threadIdx.x; i < SORTN; i += 1024) sh[i] = g_sel[n][i];
    __syncthreads();
    for (int k = 2; k <= SORTN; k <<= 1) {
        for (int j = k >> 1; j > 0; j >>= 1) {
            for (int i = threadIdx.x; i < SORTN; i += 1024) {
                int ixj = i ^ j;
                if (ixj > i) {
                    unsigned long long a = sh[i], b = sh[ixj];
                    bool up = (i & k) == 0;
                    if (up ? (a < b) : (a > b)) { sh[i] = b; sh[ixj] = a; }
                }
            }
            __syncthreads();
        }
    }
    for (int r = threadIdx.x; r < NPRE; r += 1024) {
        unsigned long long comp = sh[r];
        unsigned j = 0xFFFFFFFFu - (unsigned)(comp & 0xFFFFFFFFull);
        if (j >= NA) j = NA - 1;
        g_bsort[n][r] = g_boxes[(size_t)n * NA + j];
    }
}

// ---------------- NMS masks ----------------
__global__ __launch_bounds__(64) void masks_k() {
    int n = blockIdx.z, ci = blockIdx.y, cj = blockIdx.x;
    int t = threadIdx.x;
    int i = ci * 64 + t;
    if (cj < ci) { g_masks[n][i][cj] = 0ull; return; }
    __shared__ float4 bj[64];
    int jg = cj * 64 + t;
    bj[t] = (jg < NPRE) ? g_bsort[n][jg] : make_float4(0.f, 0.f, 0.f, 0.f);
    __syncthreads();
    if (i >= NPRE) { g_masks[n][i][cj] = 0ull; return; }
    float4 bi = g_bsort[n][i];
    float areai = (bi.z - bi.x) * (bi.w - bi.y);
    unsigned long long m = 0ull;
    int jbase = cj * 64;
    #pragma unroll 8
    for (int jj = 0; jj < 64; jj++) {
        int jgl = jbase + jj;
        if (jgl > i && jgl < NPRE) {
            float4 bb = bj[jj];
            float ty1 = fmaxf(bi.x, bb.x), tx1 = fmaxf(bi.y, bb.y);
            float ty2 = fminf(bi.z, bb.z), tx2 = fminf(bi.w, bb.w);
            float ihh = fmaxf(ty2 - ty1, 0.f), iww = fmaxf(tx2 - tx1, 0.f);
            float inter = ihh * iww;
            float areaj = (bb.z - bb.x) * (bb.w - bb.y);
            float iou = inter / (areai + areaj - inter + 1e-10f);
            if (iou > 0.7f) m |= (1ull << jj);
        }
    }
    g_masks[n][i][cj] = m;
}

// ---------------- single-warp NMS: depth-32 diagonal prefetch, boundary-only shfl ----------------
__global__ __launch_bounds__(32) void nms_emit_k(float* __restrict__ dout) {
    int n = blockIdx.x;
    int l = threadIdx.x;
    int c0 = l, c1 = l + 32, c2 = l + 64;
    bool v2 = c2 < NCHUNK;
    unsigned long long rv0 = 0, rv1 = 0, rv2 = 0;
    unsigned long long b0[8], b1[8], b2[8], mbuf[32];
    #pragma unroll
    for (int s = 0; s < 8; s++) {
        b0[s] = g_masks[n][s][c0];
        b1[s] = g_masks[n][s][c1];
        b2[s] = v2 ? g_masks[n][s][c2] : 0ull;
    }
    #pragma unroll
    for (int s = 0; s < 32; s++) mbuf[s] = g_masks[n][s][0];  // rows 0..31 in chunk 0
    unsigned long long cur = 0ull;
    for (int ib = 0; ib < NPAD; ib += 32) {
        #pragma unroll
        for (int s = 0; s < 32; s++) {
            int i = ib + s;
            unsigned long long cm0 = b0[s & 7], cm1 = b1[s & 7], cm2 = b2[s & 7];
            unsigned long long m = mbuf[s];
            if (i + 8 < NPAD) {
                b0[s & 7] = g_masks[n][i + 8][c0];
                b1[s & 7] = g_masks[n][i + 8][c1];
                b2[s & 7] = v2 ? g_masks[n][i + 8][c2] : 0ull;
            }
            if (i + 32 < NPAD) mbuf[s] = g_masks[n][i + 32][(i + 32) >> 6];
            if ((i & 63) == 0) {
                int ch = i >> 6, slot = ch >> 5, src = ch & 31;
                unsigned long long rsel = (slot == 0) ? rv0 : ((slot == 1) ? rv1 : rv2);
                cur = __shfl_sync(0xFFFFFFFFu, rsel, src);
            }
            if (i < NPRE && !((cur >> (i & 63)) & 1ull)) {
                rv0 |= cm0; rv1 |= cm1; rv2 |= cm2;
                cur |= m;
            }
        }
    }
    __shared__ unsigned long long remv[96];
    remv[l] = rv0; remv[l + 32] = rv1;
    if (v2) remv[l + 64] = rv2;
    __syncwarp();
    float* rind = dout + RIND_OFF + n * NPOST;
    for (int q = l; q < NPOST; q += 32) rind[q] = (float)n;
    if (l == 0) {
        float4* rois = (float4*)(dout + ROIS_OFF) + n * NPOST;
        int r = 0;
        for (int i = 0; i < NPRE && r < NPOST; i++)
            if (((remv[i >> 6] >> (i & 63)) & 1ull) == 0ull) rois[r++] = g_bsort[n][i];
        for (int i = 0; i < NPRE && r < NPOST; i++)
            if (((remv[i >> 6] >> (i & 63)) & 1ull) != 0ull) rois[r++] = g_bsort[n][i];
    }
}

// ---------------- launch ----------------
extern "C" void kernel_launch(void* const* d_in, const int* in_sizes, int n_in,
                              void* d_out, int out_size) {
    const float* x  = (const float*)d_in[0];
    const float* W1 = (const float*)d_in[1];
    const float* b1 = (const float*)d_in[2];
    const float* Ws = (const float*)d_in[3];
    const float* bs = (const float*)d_in[4];
    const float* Wl = (const float*)d_in[5];
    const float* bl = (const float*)d_in[6];
    const int* ih   = (const int*)d_in[7];
    const int* iw   = (const int*)d_in[8];
    float* out = (float*)d_out;

    cudaFuncSetAttribute(sort_k, cudaFuncAttributeMaxDynamicSharedMemorySize, SORTN * 8);
    cudaFuncSetAttribute(wino_mma_k, cudaFuncAttributeMaxDynamicSharedMemorySize, CONV_SMEM);

    init_k<<<(N_BATCH * SORTN + 255) / 256, 256>>>();
    xborder_k<<<(260 * 512 * N_BATCH + 255) / 256, 256>>>();
    xt_k<<<dim3(64, 8, 4), 256>>>(x);
    uwino_k<<<(COUT * CIN + 255) / 256, 256>>>(W1);
    vwino_k<<<dim3(NTILE, 2, 4), 256>>>();
    wino_mma_k<<<dim3(64, 4, 16), 256, CONV_SMEM>>>();
    owino_k<<<dim3(NTILE, 4), 512>>>(b1);
    heads_k<<<dim3(64, 4), 256>>>(Wl, bl, Ws, bs, out);
    anchors_k<<<(NA + 255) / 256, 256>>>(out);
    boxes_k<<<(N_BATCH * NA + 255) / 256, 256>>>(out, ih, iw);
    select_k<<<N_BATCH, 1024>>>();
    compact_k<<<(N_BATCH * NA + 255) / 256, 256>>>();
    sort_k<<<N_BATCH, 1024, SORTN * 8>>>();
    masks_k<<<dim3(NCHUNK, NCHUNK, N_BATCH), 64>>>();
    nms_emit_k<<<N_BATCH, 32>>>(out);
}